// round 9
// baseline (speedup 1.0000x reference)
#include <cuda_runtime.h>

#define BB 2
#define NCH 7
#define VV 2097152          // 32*256*256
#define NI 16
#define NSG 17
#define NBINS 2048
#define DGRID 128           // k_dist grid.x

// accumulator layout (floats)
#define OFF_CNT   0          // BB*NSG
#define OFF_SSUM  34         // BB*NSG*3
#define OFF_SSQ   136
#define OFF_XYZ   238
#define OFF_CCNT  340
#define OFF_CXYZ  374
#define OFF_VAR   476        // BB
#define OFF_SBG   478
#define OFF_SFG   480
#define OFF_ILOSS 482
#define OFF_S     484        // BB*NI*3  (pre-scaled by log2 e)
#define OFF_CEN   580        // BB*NI*3
#define ACC_N     676

__device__ float g_acc[ACC_N];                  // zero-init; self-cleaning
__device__ unsigned g_hfg[BB * NI * NBINS];     // 128KB fg counts
__device__ unsigned g_hbg[BB * NI * NBINS];     // 128KB bg counts
__device__ unsigned g_ticket;                   // lovasz completion ticket

__device__ __forceinline__ float fast_tanh(float x) {
    float r;
    asm("tanh.approx.f32 %0, %1;" : "=f"(r) : "f"(x));
    return r;
}
__device__ __forceinline__ float fast_ex2(float x) {
    float r;
    asm("ex2.approx.f32 %0, %1;" : "=f"(r) : "f"(x));
    return r;
}

// ---------------------------------------------------------------- stats
// Per-warp fixed-point packed accumulators (3 u64 per id), exact/bounded for
// exactly 256 voxels per warp. grid (1024, BB), 256 thr, 8 voxels/thread.
__global__ void __launch_bounds__(256) k_stats(const float* __restrict__ pred,
                                               const int* __restrict__ inst,
                                               const int* __restrict__ cent) {
    int b = blockIdx.y;
    __shared__ unsigned long long wacc[8][NSG][3];
    __shared__ float sm[NSG * 10];
    int tid = threadIdx.x;
    int warp = tid >> 5, lane = tid & 31;

    for (int j = tid; j < 8 * NSG * 3; j += 256)
        ((unsigned long long*)wacc)[j] = 0ull;
    for (int j = tid; j < NSG * 10; j += 256) sm[j] = 0.0f;
    __syncthreads();

    const float* sig = pred + ((size_t)b * NCH + 3) * VV;
    const int* ib = inst + (size_t)b * VV;
    const int* cb = cent + (size_t)b * VV;

    int v0 = (blockIdx.x * 256 + tid) * 8;
#pragma unroll
    for (int g = 0; g < 2; g++) {
        int vb = v0 + g * 4;
        float4 f0 = *(const float4*)(sig + vb);
        float4 f1 = *(const float4*)(sig + VV + vb);
        float4 f2 = *(const float4*)(sig + 2 * VV + vb);
        int4 iv = *(const int4*)(ib + vb);
        int4 cv = *(const int4*)(cb + vb);
        float a0[4] = {f0.x, f0.y, f0.z, f0.w};
        float a1[4] = {f1.x, f1.y, f1.z, f1.w};
        float a2[4] = {f2.x, f2.y, f2.z, f2.w};
        int ia[4] = {iv.x, iv.y, iv.z, iv.w};
        int ca[4] = {cv.x, cv.y, cv.z, cv.w};
#pragma unroll
        for (int k = 0; k < 4; k++) {
            int v = vb + k;
            int id = ia[k];
            float s0 = fminf(fmaxf(a0[k], -15.5f), 15.5f);
            float s1 = fminf(fmaxf(a1[k], -15.5f), 15.5f);
            float s2 = fminf(fmaxf(a2[k], -15.5f), 15.5f);
            unsigned xi = v & 255;
            unsigned yi = (v >> 8) & 255;
            unsigned zi = (unsigned)v >> 16;
            unsigned long long* base = wacc[warp][id];
            unsigned q0 = __float2uint_rn((s0 + 16.0f) * 256.0f);
            unsigned q1 = __float2uint_rn((s1 + 16.0f) * 256.0f);
            unsigned q2 = __float2uint_rn((s2 + 16.0f) * 256.0f);
            unsigned r0 = __float2uint_rn(s0 * s0 * 32.0f);
            unsigned r1 = __float2uint_rn(s1 * s1 * 32.0f);
            unsigned r2 = __float2uint_rn(s2 * s2 * 32.0f);
            atomicAdd(&base[0], (unsigned long long)xi
                                | ((unsigned long long)yi << 17)
                                | ((unsigned long long)zi << 34)
                                | (1ull << 48));
            atomicAdd(&base[1], (unsigned long long)q0
                                | ((unsigned long long)q1 << 21)
                                | ((unsigned long long)q2 << 42));
            atomicAdd(&base[2], (unsigned long long)r0
                                | ((unsigned long long)r1 << 21)
                                | ((unsigned long long)r2 << 42));
            if (ca[k] != 0) {   // centers are ~1-per-volume rare: direct global
                int bi = b * NSG + id;
                atomicAdd(&g_acc[OFF_CCNT + bi], 1.0f);
                atomicAdd(&g_acc[OFF_CXYZ + bi * 3 + 0], (float)xi * (1.0f / 1023.0f));
                atomicAdd(&g_acc[OFF_CXYZ + bi * 3 + 1], (float)yi * (1.0f / 1023.0f));
                atomicAdd(&g_acc[OFF_CXYZ + bi * 3 + 2], (float)zi * (1.0f / 31.0f));
            }
        }
    }
    __syncthreads();

    // decode per-warp packs -> block-level float accumulation
    if (lane < NSG) {
        unsigned long long pA = wacc[warp][lane][0];
        unsigned long long pB = wacc[warp][lane][1];
        unsigned long long pC = wacc[warp][lane][2];
        float cnt = (float)(unsigned)(pA >> 48);
        float xs = (float)(unsigned)(pA & 0x1FFFFu) * (1.0f / 1023.0f);
        float ys = (float)(unsigned)((pA >> 17) & 0x1FFFFu) * (1.0f / 1023.0f);
        float zs = (float)(unsigned)((pA >> 34) & 0x3FFFu) * (1.0f / 31.0f);
        float s0s = (float)(unsigned)(pB & 0x1FFFFFu) * (1.0f / 256.0f) - 16.0f * cnt;
        float s1s = (float)(unsigned)((pB >> 21) & 0x1FFFFFu) * (1.0f / 256.0f) - 16.0f * cnt;
        float s2s = (float)(unsigned)((pB >> 42) & 0x1FFFFFu) * (1.0f / 256.0f) - 16.0f * cnt;
        float r0s = (float)(unsigned)(pC & 0x1FFFFFu) * (1.0f / 32.0f);
        float r1s = (float)(unsigned)((pC >> 21) & 0x1FFFFFu) * (1.0f / 32.0f);
        float r2s = (float)(unsigned)((pC >> 42) & 0x1FFFFFu) * (1.0f / 32.0f);
        float* d = sm + lane * 10;
        atomicAdd(d + 0, cnt);
        atomicAdd(d + 1, s0s);
        atomicAdd(d + 2, s1s);
        atomicAdd(d + 3, s2s);
        atomicAdd(d + 4, r0s);
        atomicAdd(d + 5, r1s);
        atomicAdd(d + 6, r2s);
        atomicAdd(d + 7, xs);
        atomicAdd(d + 8, ys);
        atomicAdd(d + 9, zs);
    }
    __syncthreads();
    if (tid < NSG * 10) {
        int id = tid / 10, f = tid % 10;
        float vsm = sm[tid];
        if (vsm != 0.0f) {
            int bi = b * NSG + id;
            float* dst;
            if (f == 0)      dst = &g_acc[OFF_CNT  + bi];
            else if (f < 4)  dst = &g_acc[OFF_SSUM + bi * 3 + (f - 1)];
            else if (f < 7)  dst = &g_acc[OFF_SSQ  + bi * 3 + (f - 4)];
            else             dst = &g_acc[OFF_XYZ  + bi * 3 + (f - 7)];
            atomicAdd(dst, vsm);
        }
    }
}

// ---------------------------------------------------------------- params (+ zero stats accumulators)
__global__ void k_params() {
    int t = threadIdx.x;
    if (t >= BB * NSG) return;
    int b = t / NSG, id = t % NSG;
    float cnt = g_acc[OFF_CNT + t];
    float safe = fmaxf(cnt, 1.0f);
    float varsum = 0.0f;
    float m[3];
    float xyz[3], cxyz[3];
#pragma unroll
    for (int c = 0; c < 3; c++) {
        float ss = g_acc[OFF_SSUM + t * 3 + c];
        float sq = g_acc[OFF_SSQ + t * 3 + c];
        float mm = ss / safe;
        m[c] = mm;
        varsum += (sq - 2.0f * mm * ss + cnt * mm * mm) / safe;
        xyz[c] = g_acc[OFF_XYZ + t * 3 + c];
        cxyz[c] = g_acc[OFF_CXYZ + t * 3 + c];
    }
    float ccnt = g_acc[OFF_CCNT + t];
    // zero for next graph replay
    g_acc[OFF_CNT + t] = 0.0f;
    g_acc[OFF_CCNT + t] = 0.0f;
#pragma unroll
    for (int c = 0; c < 3; c++) {
        g_acc[OFF_SSUM + t * 3 + c] = 0.0f;
        g_acc[OFF_SSQ + t * 3 + c] = 0.0f;
        g_acc[OFF_XYZ + t * 3 + c] = 0.0f;
        g_acc[OFF_CXYZ + t * 3 + c] = 0.0f;
    }
    if (id >= 1) {
        atomicAdd(&g_acc[OFF_VAR + b], varsum * (1.0f / (3.0f * NI)));
        bool one = (ccnt == 1.0f);
        int p = (b * NI + (id - 1)) * 3;
#pragma unroll
        for (int c = 0; c < 3; c++) {
            float cen = one ? cxyz[c] : xyz[c] / safe;
            g_acc[OFF_CEN + p + c] = cen;
            // pre-scale by log2(e) so k_dist can use raw ex2
            g_acc[OFF_S + p + c] = expf(10.0f * m[c]) * 1.4426950408889634f;
        }
    }
}

// ---------------------------------------------------------------- nop (profiler alignment: puts k_dist at capture index 5)
__global__ void k_nop() {}

// ---------------------------------------------------------------- dist + SMEM histogram + seed loss
// grid (DGRID, BB, 2), 256 thr, 64 grid-stride iters. blockIdx.z selects 8 of
// 16 instances. Private 8-inst x 2048-bin u16-PACKED smem bg hist (32KB);
// per-(block,inst,bin) count <= 16384 < 65535, no overflow. fg -> global RED.
__global__ void __launch_bounds__(256) k_dist(const float* __restrict__ pred,
                                              const int* __restrict__ inst,
                                              const int* __restrict__ lab) {
    __shared__ unsigned shist[8 * NBINS / 2];     // 32KB, 2 bins per word
    __shared__ float r1[256], r2[256];
    int b = blockIdx.y;
    int half = blockIdx.z;           // instances [half*8, half*8+8)
    int nbase = half * 8;

    float c0[8], c1[8], c2[8], s0[8], s1[8], s2[8];
#pragma unroll
    for (int j = 0; j < 8; j++) {
        int p = (b * NI + nbase + j) * 3;
        s0[j] = g_acc[OFF_S + p];
        s1[j] = g_acc[OFF_S + p + 1];
        s2[j] = g_acc[OFF_S + p + 2];
        c0[j] = g_acc[OFF_CEN + p];
        c1[j] = g_acc[OFF_CEN + p + 1];
        c2[j] = g_acc[OFF_CEN + p + 2];
    }

    for (int i = threadIdx.x; i < 8 * NBINS / 2; i += 256) shist[i] = 0u;
    __syncthreads();

    const float* pb = pred + (size_t)b * NCH * VV;
    const int* ib = inst + (size_t)b * VV;
    const int* lb = lab + (size_t)b * VV;
    unsigned* hfg = g_hfg + (size_t)b * NI * NBINS;

    float accbg = 0.0f, accfg = 0.0f;

    for (int v = blockIdx.x * 256 + threadIdx.x; v < VV; v += DGRID * 256) {
        float x = (float)(v & 255) * (1.0f / 1023.0f);
        float y = (float)((v >> 8) & 255) * (1.0f / 1023.0f);
        float z = (float)(v >> 16) * (1.0f / 31.0f);
        float e0 = fast_tanh(pb[v]) + x;
        float e1 = fast_tanh(pb[VV + v]) + y;
        float e2 = fast_tanh(pb[2 * VV + v]) + z;
        int id = ib[v];
        float down = 0.0f;
#pragma unroll
        for (int j = 0; j < 8; j++) {
            int n = nbase + j;
            float dx = e0 - c0[j], dy = e1 - c1[j], dz = e2 - c2[j];
            float arg = s0[j] * dx * dx + s1[j] * dy * dy + s2[j] * dz * dz;
            float d = fast_ex2(-arg);               // s pre-scaled by log2 e
            bool fg = (id == n + 1);
            if (fg) down = d;
            float e = fg ? fmaf(-2.0f, d, 2.0f) : 2.0f * d;
            int bin = (int)(e * (NBINS * 0.5f));
            if (bin > NBINS - 1) bin = NBINS - 1;
            if (fg) {
                atomicAdd(&hfg[n * NBINS + bin], 1u);
            } else {
                unsigned addv = 1u << ((bin & 1) << 4);   // lo/hi u16 half
                atomicAdd(&shist[(j << 10) | (bin >> 1)], addv);
            }
        }
        bool own = (id > nbase && id <= nbase + 8);
        bool bg = (half == 0) && (lb[v] == 0);
        if (own | bg) {
            float sd = 1.0f / (1.0f + __expf(-pb[6 * VV + v]));
            if (own) {
                float t = sd - down;
                accfg += t * t;
            }
            if (bg) accbg += sd * sd;
        }
    }

    __syncthreads();
    // flush bg histogram: decode u16 halves, pre-aggregated REDs
    unsigned* dstbg = g_hbg + (size_t)(b * NI + nbase) * NBINS;
    for (int i = threadIdx.x; i < 8 * NBINS / 2; i += 256) {
        unsigned c = shist[i];
        int j = i >> 10;                  // instance within block
        int w = i & 1023;                 // word index -> bins 2w, 2w+1
        unsigned lo = c & 0xFFFFu, hi = c >> 16;
        if (lo) atomicAdd(&dstbg[j * NBINS + 2 * w], lo);
        if (hi) atomicAdd(&dstbg[j * NBINS + 2 * w + 1], hi);
    }

    int t = threadIdx.x;
    r1[t] = accbg;
    r2[t] = accfg;
    __syncthreads();
    for (int s = 128; s > 0; s >>= 1) {
        if (t < s) { r1[t] += r1[t + s]; r2[t] += r2[t + s]; }
        __syncthreads();
    }
    if (t == 0) {
        if (half == 0) atomicAdd(&g_acc[OFF_SBG + b], r1[0]);
        atomicAdd(&g_acc[OFF_SFG + b], r2[0]);
    }
}

// ---------------------------------------------------------------- lovasz (+ self-wipe + folded final)
// one block per (b,n); 1024 threads; CH=2 bins/thread; shfl-based prefix scan.
// Last block (ticket) combines all losses and writes out[0].
__global__ void __launch_bounds__(1024) k_lovasz(float* out) {
    int bn = blockIdx.x;       // b*16 + n
    int b = bn >> 4;
    unsigned* HF = g_hfg + (size_t)bn * NBINS;
    unsigned* HB = g_hbg + (size_t)bn * NBINS;
    const int CH = NBINS / 1024;  // 2
    int t = threadIdx.x;
    int lane = t & 31, warp = t >> 5;

    // load my bins (descending error order: rank r = t*CH+i, bin = NBINS-1-r)
    float fA[CH], bA[CH];
    float locF = 0.0f, locB = 0.0f;
#pragma unroll
    for (int i = 0; i < CH; i++) {
        int bin = NBINS - 1 - (t * CH + i);
        fA[i] = (float)HF[bin];
        bA[i] = (float)HB[bin];
        locF += fA[i];
        locB += bA[i];
        HF[bin] = 0u;     // self-wipe for next replay
        HB[bin] = 0u;
    }

    // warp-level inclusive scan of (locF, locB) in thread order
    float incF = locF, incB = locB;
#pragma unroll
    for (int d = 1; d < 32; d <<= 1) {
        float vF = __shfl_up_sync(0xffffffffu, incF, d);
        float vB = __shfl_up_sync(0xffffffffu, incB, d);
        if (lane >= d) { incF += vF; incB += vB; }
    }
    __shared__ float wF[32], wB[32];
    __shared__ float sred[1024];
    __shared__ int sMinR;
    if (t == 0) sMinR = NBINS;
    if (lane == 31) { wF[warp] = incF; wB[warp] = incB; }
    __syncthreads();
    float offF = 0.0f, offB = 0.0f, G = 0.0f;
#pragma unroll
    for (int w = 0; w < 32; w++) {
        float f = wF[w];
        if (w < warp) { offF += f; offB += wB[w]; }
        G += f;
    }
    float P = offF + incF - locF;   // exclusive prefix (fg)
    float Q = offB + incB - locB;   // exclusive prefix (bg)

    float contrib = 0.0f;
    if (G > 0.0f) {
#pragma unroll
        for (int i = 0; i < CH; i++) {
            float f = fA[i], bb = bA[i];
            if (f > 0.0f || bb > 0.0f) {
                int bin = NBINS - 1 - (t * CH + i);
                float e = ((float)bin + 0.5f) * (2.0f / NBINS);
                float gq = G + Q;
                float num = (G - P) * bb + f * gq;   // cancellation-free jacc delta
                float den = gq * (gq + bb);
                contrib += e * num / den;
                P += f;
                Q += bb;
            }
        }
    } else {  // degenerate: no fg voxels -> loss = max error present
#pragma unroll
        for (int i = 0; i < CH; i++) {
            if (fA[i] > 0.0f || bA[i] > 0.0f) {
                atomicMin(&sMinR, t * CH + i);
                break;
            }
        }
    }
    sred[t] = contrib;
    __syncthreads();
    for (int s2 = 512; s2 > 0; s2 >>= 1) {
        if (t < s2) sred[t] += sred[t + s2];
        __syncthreads();
    }
    if (t == 0) {
        float total = sred[0];
        if (G <= 0.0f && sMinR < NBINS)
            total = ((float)(NBINS - 1 - sMinR) + 0.5f) * (2.0f / NBINS);
        atomicAdd(&g_acc[OFF_ILOSS + b], total);
        __threadfence();
        unsigned tk = atomicAdd(&g_ticket, 1u);
        if (tk == (unsigned)(BB * NI - 1)) {        // last block: fold final
            volatile float* ga = g_acc;
            float r = 0.0f;
            for (int b2 = 0; b2 < BB; b2++) {
                float il = ga[OFF_ILOSS + b2] * (1.0f / NI);
                float vl = ga[OFF_VAR + b2];
                float sl = (ga[OFF_SBG + b2] + 10.0f * ga[OFF_SFG + b2]) * (1.0f / VV);
                r += il + 10.0f * vl + sl;
                ga[OFF_ILOSS + b2] = 0.0f;
                ga[OFF_VAR + b2] = 0.0f;
                ga[OFF_SBG + b2] = 0.0f;
                ga[OFF_SFG + b2] = 0.0f;
            }
            out[0] = r * (1.0f / BB);
            g_ticket = 0u;                           // reset for next replay
        }
    }
}

// ---------------------------------------------------------------- launch
extern "C" void kernel_launch(void* const* d_in, const int* in_sizes, int n_in,
                              void* d_out, int out_size) {
    const float* pred = (const float*)d_in[0];
    const int* inst = (const int*)d_in[1];
    const int* lab = (const int*)d_in[2];
    const int* cent = (const int*)d_in[3];

    {
        dim3 g(1024, BB);
        k_stats<<<g, 256>>>(pred, inst, cent);
    }
    k_params<<<1, 64>>>();
    k_nop<<<1, 1>>>();   // aligns ncu capture (-s 5) onto k_dist
    {
        dim3 g(DGRID, BB, 2);
        k_dist<<<g, 256>>>(pred, inst, lab);
    }
    k_lovasz<<<BB * NI, 1024>>>((float*)d_out);
}

// round 10
// speedup vs baseline: 1.1153x; 1.1153x over previous
#include <cuda_runtime.h>

#define BB 2
#define NCH 7
#define VV 2097152          // 32*256*256
#define NI 16
#define NSG 17
#define NBINS 2048
#define DGRID 128           // k_dist grid.x

// accumulator layout (floats)
#define OFF_CNT   0          // BB*NSG
#define OFF_SSUM  34         // BB*NSG*3
#define OFF_SSQ   136
#define OFF_XYZ   238
#define OFF_CCNT  340
#define OFF_CXYZ  374
#define OFF_VAR   476        // BB
#define OFF_SBG   478
#define OFF_SFG   480
#define OFF_ILOSS 482
#define OFF_S     484        // BB*NI*3  (pre-scaled by log2 e)
#define OFF_CEN   580        // BB*NI*3
#define ACC_N     676

__device__ float g_acc[ACC_N];                  // zero-init; self-cleaning
__device__ unsigned g_hfg[BB * NI * NBINS];     // 128KB fg counts
__device__ unsigned g_hbg[BB * NI * NBINS];     // 128KB bg counts
__device__ unsigned g_ticket;                   // lovasz completion ticket

__device__ __forceinline__ float fast_tanh(float x) {
    float r;
    asm("tanh.approx.f32 %0, %1;" : "=f"(r) : "f"(x));
    return r;
}
__device__ __forceinline__ float fast_ex2(float x) {
    float r;
    asm("ex2.approx.f32 %0, %1;" : "=f"(r) : "f"(x));
    return r;
}

// ---------------------------------------------------------------- stats
// Per-warp fixed-point packed accumulators (3 u64 per id), exact/bounded for
// exactly 256 voxels per warp. grid (1024, BB), 256 thr, 8 voxels/thread.
__global__ void __launch_bounds__(256) k_stats(const float* __restrict__ pred,
                                               const int* __restrict__ inst,
                                               const int* __restrict__ cent) {
    int b = blockIdx.y;
    __shared__ unsigned long long wacc[8][NSG][3];
    __shared__ float sm[NSG * 10];
    int tid = threadIdx.x;
    int warp = tid >> 5, lane = tid & 31;

    for (int j = tid; j < 8 * NSG * 3; j += 256)
        ((unsigned long long*)wacc)[j] = 0ull;
    for (int j = tid; j < NSG * 10; j += 256) sm[j] = 0.0f;
    __syncthreads();

    const float* sig = pred + ((size_t)b * NCH + 3) * VV;
    const int* ib = inst + (size_t)b * VV;
    const int* cb = cent + (size_t)b * VV;

    int v0 = (blockIdx.x * 256 + tid) * 8;
#pragma unroll
    for (int g = 0; g < 2; g++) {
        int vb = v0 + g * 4;
        float4 f0 = *(const float4*)(sig + vb);
        float4 f1 = *(const float4*)(sig + VV + vb);
        float4 f2 = *(const float4*)(sig + 2 * VV + vb);
        int4 iv = *(const int4*)(ib + vb);
        int4 cv = *(const int4*)(cb + vb);
        float a0[4] = {f0.x, f0.y, f0.z, f0.w};
        float a1[4] = {f1.x, f1.y, f1.z, f1.w};
        float a2[4] = {f2.x, f2.y, f2.z, f2.w};
        int ia[4] = {iv.x, iv.y, iv.z, iv.w};
        int ca[4] = {cv.x, cv.y, cv.z, cv.w};
#pragma unroll
        for (int k = 0; k < 4; k++) {
            int v = vb + k;
            int id = ia[k];
            float s0 = fminf(fmaxf(a0[k], -15.5f), 15.5f);
            float s1 = fminf(fmaxf(a1[k], -15.5f), 15.5f);
            float s2 = fminf(fmaxf(a2[k], -15.5f), 15.5f);
            unsigned xi = v & 255;
            unsigned yi = (v >> 8) & 255;
            unsigned zi = (unsigned)v >> 16;
            unsigned long long* base = wacc[warp][id];
            unsigned q0 = __float2uint_rn((s0 + 16.0f) * 256.0f);
            unsigned q1 = __float2uint_rn((s1 + 16.0f) * 256.0f);
            unsigned q2 = __float2uint_rn((s2 + 16.0f) * 256.0f);
            unsigned r0 = __float2uint_rn(s0 * s0 * 32.0f);
            unsigned r1 = __float2uint_rn(s1 * s1 * 32.0f);
            unsigned r2 = __float2uint_rn(s2 * s2 * 32.0f);
            atomicAdd(&base[0], (unsigned long long)xi
                                | ((unsigned long long)yi << 17)
                                | ((unsigned long long)zi << 34)
                                | (1ull << 48));
            atomicAdd(&base[1], (unsigned long long)q0
                                | ((unsigned long long)q1 << 21)
                                | ((unsigned long long)q2 << 42));
            atomicAdd(&base[2], (unsigned long long)r0
                                | ((unsigned long long)r1 << 21)
                                | ((unsigned long long)r2 << 42));
            if (ca[k] != 0) {   // centers are ~1-per-volume rare: direct global
                int bi = b * NSG + id;
                atomicAdd(&g_acc[OFF_CCNT + bi], 1.0f);
                atomicAdd(&g_acc[OFF_CXYZ + bi * 3 + 0], (float)xi * (1.0f / 1023.0f));
                atomicAdd(&g_acc[OFF_CXYZ + bi * 3 + 1], (float)yi * (1.0f / 1023.0f));
                atomicAdd(&g_acc[OFF_CXYZ + bi * 3 + 2], (float)zi * (1.0f / 31.0f));
            }
        }
    }
    __syncthreads();

    // decode per-warp packs -> block-level float accumulation
    if (lane < NSG) {
        unsigned long long pA = wacc[warp][lane][0];
        unsigned long long pB = wacc[warp][lane][1];
        unsigned long long pC = wacc[warp][lane][2];
        float cnt = (float)(unsigned)(pA >> 48);
        float xs = (float)(unsigned)(pA & 0x1FFFFu) * (1.0f / 1023.0f);
        float ys = (float)(unsigned)((pA >> 17) & 0x1FFFFu) * (1.0f / 1023.0f);
        float zs = (float)(unsigned)((pA >> 34) & 0x3FFFu) * (1.0f / 31.0f);
        float s0s = (float)(unsigned)(pB & 0x1FFFFFu) * (1.0f / 256.0f) - 16.0f * cnt;
        float s1s = (float)(unsigned)((pB >> 21) & 0x1FFFFFu) * (1.0f / 256.0f) - 16.0f * cnt;
        float s2s = (float)(unsigned)((pB >> 42) & 0x1FFFFFu) * (1.0f / 256.0f) - 16.0f * cnt;
        float r0s = (float)(unsigned)(pC & 0x1FFFFFu) * (1.0f / 32.0f);
        float r1s = (float)(unsigned)((pC >> 21) & 0x1FFFFFu) * (1.0f / 32.0f);
        float r2s = (float)(unsigned)((pC >> 42) & 0x1FFFFFu) * (1.0f / 32.0f);
        float* d = sm + lane * 10;
        atomicAdd(d + 0, cnt);
        atomicAdd(d + 1, s0s);
        atomicAdd(d + 2, s1s);
        atomicAdd(d + 3, s2s);
        atomicAdd(d + 4, r0s);
        atomicAdd(d + 5, r1s);
        atomicAdd(d + 6, r2s);
        atomicAdd(d + 7, xs);
        atomicAdd(d + 8, ys);
        atomicAdd(d + 9, zs);
    }
    __syncthreads();
    if (tid < NSG * 10) {
        int id = tid / 10, f = tid % 10;
        float vsm = sm[tid];
        if (vsm != 0.0f) {
            int bi = b * NSG + id;
            float* dst;
            if (f == 0)      dst = &g_acc[OFF_CNT  + bi];
            else if (f < 4)  dst = &g_acc[OFF_SSUM + bi * 3 + (f - 1)];
            else if (f < 7)  dst = &g_acc[OFF_SSQ  + bi * 3 + (f - 4)];
            else             dst = &g_acc[OFF_XYZ  + bi * 3 + (f - 7)];
            atomicAdd(dst, vsm);
        }
    }
}

// ---------------------------------------------------------------- params (+ zero stats accumulators)
__global__ void k_params() {
    int t = threadIdx.x;
    if (t >= BB * NSG) return;
    int b = t / NSG, id = t % NSG;
    float cnt = g_acc[OFF_CNT + t];
    float safe = fmaxf(cnt, 1.0f);
    float varsum = 0.0f;
    float m[3];
    float xyz[3], cxyz[3];
#pragma unroll
    for (int c = 0; c < 3; c++) {
        float ss = g_acc[OFF_SSUM + t * 3 + c];
        float sq = g_acc[OFF_SSQ + t * 3 + c];
        float mm = ss / safe;
        m[c] = mm;
        varsum += (sq - 2.0f * mm * ss + cnt * mm * mm) / safe;
        xyz[c] = g_acc[OFF_XYZ + t * 3 + c];
        cxyz[c] = g_acc[OFF_CXYZ + t * 3 + c];
    }
    float ccnt = g_acc[OFF_CCNT + t];
    // zero for next graph replay
    g_acc[OFF_CNT + t] = 0.0f;
    g_acc[OFF_CCNT + t] = 0.0f;
#pragma unroll
    for (int c = 0; c < 3; c++) {
        g_acc[OFF_SSUM + t * 3 + c] = 0.0f;
        g_acc[OFF_SSQ + t * 3 + c] = 0.0f;
        g_acc[OFF_XYZ + t * 3 + c] = 0.0f;
        g_acc[OFF_CXYZ + t * 3 + c] = 0.0f;
    }
    if (id >= 1) {
        atomicAdd(&g_acc[OFF_VAR + b], varsum * (1.0f / (3.0f * NI)));
        bool one = (ccnt == 1.0f);
        int p = (b * NI + (id - 1)) * 3;
#pragma unroll
        for (int c = 0; c < 3; c++) {
            float cen = one ? cxyz[c] : xyz[c] / safe;
            g_acc[OFF_CEN + p + c] = cen;
            // pre-scale by log2(e) so k_dist can use raw ex2
            g_acc[OFF_S + p + c] = expf(10.0f * m[c]) * 1.4426950408889634f;
        }
    }
}

// ---------------------------------------------------------------- nop (profiler alignment: puts k_dist at capture index 5)
__global__ void k_nop() {}

// ---------------------------------------------------------------- dist + SMEM histogram + seed loss
// grid (DGRID, BB, 4), 256 thr, 64 grid-stride iters (16384 voxels/block).
// blockIdx.z selects 4 of 16 instances (24 param regs). Private u16-packed
// 4-inst x 2048-bin smem bg hist (16KB); per-(block,inst,bin) <= 16384 <
// 65535, no overflow. fg -> global RED. Forced 4 blocks/SM via launch bounds.
__global__ void __launch_bounds__(256, 4) k_dist(const float* __restrict__ pred,
                                                 const int* __restrict__ inst,
                                                 const int* __restrict__ lab) {
    __shared__ unsigned shist[4 * NBINS / 2];     // 16KB, 2 bins per u32 word
    __shared__ float r1[256], r2[256];
    int b = blockIdx.y;
    int quart = blockIdx.z;          // instances [quart*4, quart*4+4)
    int nbase = quart * 4;

    float c0[4], c1[4], c2[4], s0[4], s1[4], s2[4];
#pragma unroll
    for (int j = 0; j < 4; j++) {
        int p = (b * NI + nbase + j) * 3;
        s0[j] = g_acc[OFF_S + p];
        s1[j] = g_acc[OFF_S + p + 1];
        s2[j] = g_acc[OFF_S + p + 2];
        c0[j] = g_acc[OFF_CEN + p];
        c1[j] = g_acc[OFF_CEN + p + 1];
        c2[j] = g_acc[OFF_CEN + p + 2];
    }

    for (int i = threadIdx.x; i < 4 * NBINS / 2; i += 256) shist[i] = 0u;
    __syncthreads();

    const float* pb = pred + (size_t)b * NCH * VV;
    const int* ib = inst + (size_t)b * VV;
    const int* lb = lab + (size_t)b * VV;
    unsigned* hfg = g_hfg + (size_t)b * NI * NBINS;

    float accbg = 0.0f, accfg = 0.0f;

    for (int v = blockIdx.x * 256 + threadIdx.x; v < VV; v += DGRID * 256) {
        float x = (float)(v & 255) * (1.0f / 1023.0f);
        float y = (float)((v >> 8) & 255) * (1.0f / 1023.0f);
        float z = (float)(v >> 16) * (1.0f / 31.0f);
        float e0 = fast_tanh(pb[v]) + x;
        float e1 = fast_tanh(pb[VV + v]) + y;
        float e2 = fast_tanh(pb[2 * VV + v]) + z;
        int id = ib[v];
        float down = 0.0f;
#pragma unroll
        for (int j = 0; j < 4; j++) {
            int n = nbase + j;
            float dx = e0 - c0[j], dy = e1 - c1[j], dz = e2 - c2[j];
            float arg = s0[j] * dx * dx + s1[j] * dy * dy + s2[j] * dz * dz;
            float d = fast_ex2(-arg);               // s pre-scaled by log2 e
            bool fg = (id == n + 1);
            if (fg) down = d;
            float e = fg ? fmaf(-2.0f, d, 2.0f) : 2.0f * d;
            int bin = (int)(e * (NBINS * 0.5f));
            if (bin > NBINS - 1) bin = NBINS - 1;
            if (fg) {
                atomicAdd(&hfg[n * NBINS + bin], 1u);
            } else {
                unsigned addv = 1u << ((bin & 1) << 4);   // lo/hi u16 half
                atomicAdd(&shist[(j << 10) | (bin >> 1)], addv);
            }
        }
        bool own = (id > nbase && id <= nbase + 4);
        bool bg = (quart == 0) && (lb[v] == 0);
        if (own | bg) {
            float sd = 1.0f / (1.0f + __expf(-pb[6 * VV + v]));
            if (own) {
                float t = sd - down;
                accfg += t * t;
            }
            if (bg) accbg += sd * sd;
        }
    }

    __syncthreads();
    // flush bg histogram: decode u16 halves, pre-aggregated REDs
    unsigned* dstbg = g_hbg + (size_t)(b * NI + nbase) * NBINS;
    for (int i = threadIdx.x; i < 4 * NBINS / 2; i += 256) {
        unsigned c = shist[i];
        int j = i >> 10;                  // instance within block
        int w = i & 1023;                 // word index -> bins 2w, 2w+1
        unsigned lo = c & 0xFFFFu, hi = c >> 16;
        if (lo) atomicAdd(&dstbg[j * NBINS + 2 * w], lo);
        if (hi) atomicAdd(&dstbg[j * NBINS + 2 * w + 1], hi);
    }

    int t = threadIdx.x;
    r1[t] = accbg;
    r2[t] = accfg;
    __syncthreads();
    for (int s = 128; s > 0; s >>= 1) {
        if (t < s) { r1[t] += r1[t + s]; r2[t] += r2[t + s]; }
        __syncthreads();
    }
    if (t == 0) {
        if (quart == 0) atomicAdd(&g_acc[OFF_SBG + b], r1[0]);
        atomicAdd(&g_acc[OFF_SFG + b], r2[0]);
    }
}

// ---------------------------------------------------------------- lovasz (+ self-wipe + folded final)
// one block per (b,n); 1024 threads; CH=2 bins/thread; shfl-based prefix scan.
// Last block (ticket) combines all losses and writes out[0].
__global__ void __launch_bounds__(1024) k_lovasz(float* out) {
    int bn = blockIdx.x;       // b*16 + n
    int b = bn >> 4;
    unsigned* HF = g_hfg + (size_t)bn * NBINS;
    unsigned* HB = g_hbg + (size_t)bn * NBINS;
    const int CH = NBINS / 1024;  // 2
    int t = threadIdx.x;
    int lane = t & 31, warp = t >> 5;

    // load my bins (descending error order: rank r = t*CH+i, bin = NBINS-1-r)
    float fA[CH], bA[CH];
    float locF = 0.0f, locB = 0.0f;
#pragma unroll
    for (int i = 0; i < CH; i++) {
        int bin = NBINS - 1 - (t * CH + i);
        fA[i] = (float)HF[bin];
        bA[i] = (float)HB[bin];
        locF += fA[i];
        locB += bA[i];
        HF[bin] = 0u;     // self-wipe for next replay
        HB[bin] = 0u;
    }

    // warp-level inclusive scan of (locF, locB) in thread order
    float incF = locF, incB = locB;
#pragma unroll
    for (int d = 1; d < 32; d <<= 1) {
        float vF = __shfl_up_sync(0xffffffffu, incF, d);
        float vB = __shfl_up_sync(0xffffffffu, incB, d);
        if (lane >= d) { incF += vF; incB += vB; }
    }
    __shared__ float wF[32], wB[32];
    __shared__ float sred[1024];
    __shared__ int sMinR;
    if (t == 0) sMinR = NBINS;
    if (lane == 31) { wF[warp] = incF; wB[warp] = incB; }
    __syncthreads();
    float offF = 0.0f, offB = 0.0f, G = 0.0f;
#pragma unroll
    for (int w = 0; w < 32; w++) {
        float f = wF[w];
        if (w < warp) { offF += f; offB += wB[w]; }
        G += f;
    }
    float P = offF + incF - locF;   // exclusive prefix (fg)
    float Q = offB + incB - locB;   // exclusive prefix (bg)

    float contrib = 0.0f;
    if (G > 0.0f) {
#pragma unroll
        for (int i = 0; i < CH; i++) {
            float f = fA[i], bb = bA[i];
            if (f > 0.0f || bb > 0.0f) {
                int bin = NBINS - 1 - (t * CH + i);
                float e = ((float)bin + 0.5f) * (2.0f / NBINS);
                float gq = G + Q;
                float num = (G - P) * bb + f * gq;   // cancellation-free jacc delta
                float den = gq * (gq + bb);
                contrib += e * num / den;
                P += f;
                Q += bb;
            }
        }
    } else {  // degenerate: no fg voxels -> loss = max error present
#pragma unroll
        for (int i = 0; i < CH; i++) {
            if (fA[i] > 0.0f || bA[i] > 0.0f) {
                atomicMin(&sMinR, t * CH + i);
                break;
            }
        }
    }
    sred[t] = contrib;
    __syncthreads();
    for (int s2 = 512; s2 > 0; s2 >>= 1) {
        if (t < s2) sred[t] += sred[t + s2];
        __syncthreads();
    }
    if (t == 0) {
        float total = sred[0];
        if (G <= 0.0f && sMinR < NBINS)
            total = ((float)(NBINS - 1 - sMinR) + 0.5f) * (2.0f / NBINS);
        atomicAdd(&g_acc[OFF_ILOSS + b], total);
        __threadfence();
        unsigned tk = atomicAdd(&g_ticket, 1u);
        if (tk == (unsigned)(BB * NI - 1)) {        // last block: fold final
            volatile float* ga = g_acc;
            float r = 0.0f;
            for (int b2 = 0; b2 < BB; b2++) {
                float il = ga[OFF_ILOSS + b2] * (1.0f / NI);
                float vl = ga[OFF_VAR + b2];
                float sl = (ga[OFF_SBG + b2] + 10.0f * ga[OFF_SFG + b2]) * (1.0f / VV);
                r += il + 10.0f * vl + sl;
                ga[OFF_ILOSS + b2] = 0.0f;
                ga[OFF_VAR + b2] = 0.0f;
                ga[OFF_SBG + b2] = 0.0f;
                ga[OFF_SFG + b2] = 0.0f;
            }
            out[0] = r * (1.0f / BB);
            g_ticket = 0u;                           // reset for next replay
        }
    }
}

// ---------------------------------------------------------------- launch
extern "C" void kernel_launch(void* const* d_in, const int* in_sizes, int n_in,
                              void* d_out, int out_size) {
    const float* pred = (const float*)d_in[0];
    const int* inst = (const int*)d_in[1];
    const int* lab = (const int*)d_in[2];
    const int* cent = (const int*)d_in[3];

    {
        dim3 g(1024, BB);
        k_stats<<<g, 256>>>(pred, inst, cent);
    }
    k_params<<<1, 64>>>();
    k_nop<<<1, 1>>>();   // aligns ncu capture (-s 5) onto k_dist
    {
        dim3 g(DGRID, BB, 4);
        k_dist<<<g, 256>>>(pred, inst, lab);
    }
    k_lovasz<<<BB * NI, 1024>>>((float*)d_out);
}

// round 11
// speedup vs baseline: 1.4565x; 1.3060x over previous
#include <cuda_runtime.h>

#define BB 2
#define NCH 7
#define VV 2097152          // 32*256*256
#define NI 16
#define NSG 17
#define NBINS 2048
#define DGRID 74            // k_dist grid.x: 74*2*4 = 592 = 4 blocks/SM * 148 SMs

// accumulator layout (floats)
#define OFF_CNT   0          // BB*NSG
#define OFF_SSUM  34         // BB*NSG*3
#define OFF_SSQ   136
#define OFF_XYZ   238
#define OFF_CCNT  340
#define OFF_CXYZ  374
#define OFF_VAR   476        // BB
#define OFF_SBG   478
#define OFF_SFG   480
#define OFF_ILOSS 482
#define OFF_S     484        // BB*NI*3  (NEGATED, pre-scaled by log2 e)
#define OFF_CEN   580        // BB*NI*3
#define ACC_N     676

__device__ float g_acc[ACC_N];                  // zero-init; self-cleaning
__device__ unsigned g_hfg[BB * NI * NBINS];     // 128KB fg counts
__device__ unsigned g_hbg[BB * NI * NBINS];     // 128KB bg counts
__device__ unsigned g_ticket;                   // lovasz completion ticket

__device__ __forceinline__ float fast_tanh(float x) {
    float r;
    asm("tanh.approx.f32 %0, %1;" : "=f"(r) : "f"(x));
    return r;
}
__device__ __forceinline__ float fast_ex2(float x) {
    float r;
    asm("ex2.approx.f32 %0, %1;" : "=f"(r) : "f"(x));
    return r;
}

// ---------------------------------------------------------------- stats
// Per-warp fixed-point packed accumulators (3 u64 per id), exact/bounded for
// exactly 256 voxels per warp. grid (1024, BB), 256 thr, 8 voxels/thread.
__global__ void __launch_bounds__(256) k_stats(const float* __restrict__ pred,
                                               const int* __restrict__ inst,
                                               const int* __restrict__ cent) {
    int b = blockIdx.y;
    __shared__ unsigned long long wacc[8][NSG][3];
    __shared__ float sm[NSG * 10];
    int tid = threadIdx.x;
    int warp = tid >> 5, lane = tid & 31;

    for (int j = tid; j < 8 * NSG * 3; j += 256)
        ((unsigned long long*)wacc)[j] = 0ull;
    for (int j = tid; j < NSG * 10; j += 256) sm[j] = 0.0f;
    __syncthreads();

    const float* sig = pred + ((size_t)b * NCH + 3) * VV;
    const int* ib = inst + (size_t)b * VV;
    const int* cb = cent + (size_t)b * VV;

    int v0 = (blockIdx.x * 256 + tid) * 8;
#pragma unroll
    for (int g = 0; g < 2; g++) {
        int vb = v0 + g * 4;
        float4 f0 = *(const float4*)(sig + vb);
        float4 f1 = *(const float4*)(sig + VV + vb);
        float4 f2 = *(const float4*)(sig + 2 * VV + vb);
        int4 iv = *(const int4*)(ib + vb);
        int4 cv = *(const int4*)(cb + vb);
        float a0[4] = {f0.x, f0.y, f0.z, f0.w};
        float a1[4] = {f1.x, f1.y, f1.z, f1.w};
        float a2[4] = {f2.x, f2.y, f2.z, f2.w};
        int ia[4] = {iv.x, iv.y, iv.z, iv.w};
        int ca[4] = {cv.x, cv.y, cv.z, cv.w};
#pragma unroll
        for (int k = 0; k < 4; k++) {
            int v = vb + k;
            int id = ia[k];
            float s0 = fminf(fmaxf(a0[k], -15.5f), 15.5f);
            float s1 = fminf(fmaxf(a1[k], -15.5f), 15.5f);
            float s2 = fminf(fmaxf(a2[k], -15.5f), 15.5f);
            unsigned xi = v & 255;
            unsigned yi = (v >> 8) & 255;
            unsigned zi = (unsigned)v >> 16;
            unsigned long long* base = wacc[warp][id];
            unsigned q0 = __float2uint_rn((s0 + 16.0f) * 256.0f);
            unsigned q1 = __float2uint_rn((s1 + 16.0f) * 256.0f);
            unsigned q2 = __float2uint_rn((s2 + 16.0f) * 256.0f);
            unsigned r0 = __float2uint_rn(s0 * s0 * 32.0f);
            unsigned r1 = __float2uint_rn(s1 * s1 * 32.0f);
            unsigned r2 = __float2uint_rn(s2 * s2 * 32.0f);
            atomicAdd(&base[0], (unsigned long long)xi
                                | ((unsigned long long)yi << 17)
                                | ((unsigned long long)zi << 34)
                                | (1ull << 48));
            atomicAdd(&base[1], (unsigned long long)q0
                                | ((unsigned long long)q1 << 21)
                                | ((unsigned long long)q2 << 42));
            atomicAdd(&base[2], (unsigned long long)r0
                                | ((unsigned long long)r1 << 21)
                                | ((unsigned long long)r2 << 42));
            if (ca[k] != 0) {   // centers are ~1-per-volume rare: direct global
                int bi = b * NSG + id;
                atomicAdd(&g_acc[OFF_CCNT + bi], 1.0f);
                atomicAdd(&g_acc[OFF_CXYZ + bi * 3 + 0], (float)xi * (1.0f / 1023.0f));
                atomicAdd(&g_acc[OFF_CXYZ + bi * 3 + 1], (float)yi * (1.0f / 1023.0f));
                atomicAdd(&g_acc[OFF_CXYZ + bi * 3 + 2], (float)zi * (1.0f / 31.0f));
            }
        }
    }
    __syncthreads();

    // decode per-warp packs -> block-level float accumulation
    if (lane < NSG) {
        unsigned long long pA = wacc[warp][lane][0];
        unsigned long long pB = wacc[warp][lane][1];
        unsigned long long pC = wacc[warp][lane][2];
        float cnt = (float)(unsigned)(pA >> 48);
        float xs = (float)(unsigned)(pA & 0x1FFFFu) * (1.0f / 1023.0f);
        float ys = (float)(unsigned)((pA >> 17) & 0x1FFFFu) * (1.0f / 1023.0f);
        float zs = (float)(unsigned)((pA >> 34) & 0x3FFFu) * (1.0f / 31.0f);
        float s0s = (float)(unsigned)(pB & 0x1FFFFFu) * (1.0f / 256.0f) - 16.0f * cnt;
        float s1s = (float)(unsigned)((pB >> 21) & 0x1FFFFFu) * (1.0f / 256.0f) - 16.0f * cnt;
        float s2s = (float)(unsigned)((pB >> 42) & 0x1FFFFFu) * (1.0f / 256.0f) - 16.0f * cnt;
        float r0s = (float)(unsigned)(pC & 0x1FFFFFu) * (1.0f / 32.0f);
        float r1s = (float)(unsigned)((pC >> 21) & 0x1FFFFFu) * (1.0f / 32.0f);
        float r2s = (float)(unsigned)((pC >> 42) & 0x1FFFFFu) * (1.0f / 32.0f);
        float* d = sm + lane * 10;
        atomicAdd(d + 0, cnt);
        atomicAdd(d + 1, s0s);
        atomicAdd(d + 2, s1s);
        atomicAdd(d + 3, s2s);
        atomicAdd(d + 4, r0s);
        atomicAdd(d + 5, r1s);
        atomicAdd(d + 6, r2s);
        atomicAdd(d + 7, xs);
        atomicAdd(d + 8, ys);
        atomicAdd(d + 9, zs);
    }
    __syncthreads();
    if (tid < NSG * 10) {
        int id = tid / 10, f = tid % 10;
        float vsm = sm[tid];
        if (vsm != 0.0f) {
            int bi = b * NSG + id;
            float* dst;
            if (f == 0)      dst = &g_acc[OFF_CNT  + bi];
            else if (f < 4)  dst = &g_acc[OFF_SSUM + bi * 3 + (f - 1)];
            else if (f < 7)  dst = &g_acc[OFF_SSQ  + bi * 3 + (f - 4)];
            else             dst = &g_acc[OFF_XYZ  + bi * 3 + (f - 7)];
            atomicAdd(dst, vsm);
        }
    }
}

// ---------------------------------------------------------------- params (+ zero stats accumulators)
__global__ void k_params() {
    int t = threadIdx.x;
    if (t >= BB * NSG) return;
    int b = t / NSG, id = t % NSG;
    float cnt = g_acc[OFF_CNT + t];
    float safe = fmaxf(cnt, 1.0f);
    float varsum = 0.0f;
    float m[3];
    float xyz[3], cxyz[3];
#pragma unroll
    for (int c = 0; c < 3; c++) {
        float ss = g_acc[OFF_SSUM + t * 3 + c];
        float sq = g_acc[OFF_SSQ + t * 3 + c];
        float mm = ss / safe;
        m[c] = mm;
        varsum += (sq - 2.0f * mm * ss + cnt * mm * mm) / safe;
        xyz[c] = g_acc[OFF_XYZ + t * 3 + c];
        cxyz[c] = g_acc[OFF_CXYZ + t * 3 + c];
    }
    float ccnt = g_acc[OFF_CCNT + t];
    // zero for next graph replay
    g_acc[OFF_CNT + t] = 0.0f;
    g_acc[OFF_CCNT + t] = 0.0f;
#pragma unroll
    for (int c = 0; c < 3; c++) {
        g_acc[OFF_SSUM + t * 3 + c] = 0.0f;
        g_acc[OFF_SSQ + t * 3 + c] = 0.0f;
        g_acc[OFF_XYZ + t * 3 + c] = 0.0f;
        g_acc[OFF_CXYZ + t * 3 + c] = 0.0f;
    }
    if (id >= 1) {
        atomicAdd(&g_acc[OFF_VAR + b], varsum * (1.0f / (3.0f * NI)));
        bool one = (ccnt == 1.0f);
        int p = (b * NI + (id - 1)) * 3;
#pragma unroll
        for (int c = 0; c < 3; c++) {
            float cen = one ? cxyz[c] : xyz[c] / safe;
            g_acc[OFF_CEN + p + c] = cen;
            // NEGATED + pre-scaled by log2(e): k_dist computes d = ex2(sum)
            g_acc[OFF_S + p + c] = -expf(10.0f * m[c]) * 1.4426950408889634f;
        }
    }
}

// ---------------------------------------------------------------- nop (profiler alignment: puts k_dist at capture index 5)
__global__ void k_nop() {}

// ---------------------------------------------------------------- dist + SMEM histogram + seed loss
// grid (DGRID, BB, 4) = 592 blocks = single full wave (4 blocks/SM).
// blockIdx.z selects 4 of 16 instances (24 param regs). Unified u16-packed
// smem hist: regions [0..3]=bg inst, [4..7]=fg inst, 1024 u32 words each
// (32KB). Max count per (block,inst,bin) <= 28416 < 65535, no overflow.
__global__ void __launch_bounds__(256, 4) k_dist(const float* __restrict__ pred,
                                                 const int* __restrict__ inst,
                                                 const int* __restrict__ lab) {
    __shared__ unsigned shist[8 * NBINS / 2];     // 32KB
    __shared__ float r1[256], r2[256];
    int b = blockIdx.y;
    int quart = blockIdx.z;          // instances [quart*4, quart*4+4)
    int nbase = quart * 4;

    float c0[4], c1[4], c2[4], s0[4], s1[4], s2[4];
#pragma unroll
    for (int j = 0; j < 4; j++) {
        int p = (b * NI + nbase + j) * 3;
        s0[j] = g_acc[OFF_S + p];            // negative, log2e-scaled
        s1[j] = g_acc[OFF_S + p + 1];
        s2[j] = g_acc[OFF_S + p + 2];
        c0[j] = g_acc[OFF_CEN + p];
        c1[j] = g_acc[OFF_CEN + p + 1];
        c2[j] = g_acc[OFF_CEN + p + 2];
    }

    for (int i = threadIdx.x; i < 8 * NBINS / 2; i += 256) shist[i] = 0u;
    __syncthreads();

    const float* pb = pred + (size_t)b * NCH * VV;
    const int* ib = inst + (size_t)b * VV;
    const int* lb = lab + (size_t)b * VV;

    float accbg = 0.0f, accfg = 0.0f;

    for (int v = blockIdx.x * 256 + threadIdx.x; v < VV; v += DGRID * 256) {
        float x = (float)(v & 255) * (1.0f / 1023.0f);
        float y = (float)((v >> 8) & 255) * (1.0f / 1023.0f);
        float z = (float)(v >> 16) * (1.0f / 31.0f);
        float e0 = fast_tanh(pb[v]) + x;
        float e1 = fast_tanh(pb[VV + v]) + y;
        float e2 = fast_tanh(pb[2 * VV + v]) + z;
        int id = ib[v];
        float down = 0.0f;
#pragma unroll
        for (int j = 0; j < 4; j++) {
            int n = nbase + j;
            float dx = e0 - c0[j], dy = e1 - c1[j], dz = e2 - c2[j];
            float arg = s0[j] * dx * dx + s1[j] * dy * dy + s2[j] * dz * dz;
            float d = fast_ex2(arg);                // s already negative
            int fg = (id == n + 1) ? 1 : 0;
            if (fg) down = d;
            float e = fg ? fmaf(-2.0f, d, 2.0f) : 2.0f * d;
            int bin = (int)(e * (NBINS * 0.5f));
            if (bin > NBINS - 1) bin = NBINS - 1;
            // unified smem hist: region = j + 4*fg
            unsigned addv = 1u << ((bin & 1) << 4);
            atomicAdd(&shist[((j + (fg << 2)) << 10) | (bin >> 1)], addv);
        }
        bool own = (id > nbase && id <= nbase + 4);
        bool bg = (quart == 0) && (lb[v] == 0);
        if (own | bg) {
            float sd = 1.0f / (1.0f + __expf(-pb[6 * VV + v]));
            if (own) {
                float t = sd - down;
                accfg += t * t;
            }
            if (bg) accbg += sd * sd;
        }
    }

    __syncthreads();
    // flush: decode u16 halves, pre-aggregated REDs to global fg/bg hists
    for (int i = threadIdx.x; i < 8 * NBINS / 2; i += 256) {
        unsigned c = shist[i];
        int region = i >> 10;             // 0..7
        int j = region & 3;
        unsigned* dst = (region & 4) ? g_hfg : g_hbg;
        dst += (size_t)(b * NI + nbase + j) * NBINS;
        int w = i & 1023;                 // word -> bins 2w, 2w+1
        unsigned lo = c & 0xFFFFu, hi = c >> 16;
        if (lo) atomicAdd(&dst[2 * w], lo);
        if (hi) atomicAdd(&dst[2 * w + 1], hi);
    }

    int t = threadIdx.x;
    r1[t] = accbg;
    r2[t] = accfg;
    __syncthreads();
    for (int s = 128; s > 0; s >>= 1) {
        if (t < s) { r1[t] += r1[t + s]; r2[t] += r2[t + s]; }
        __syncthreads();
    }
    if (t == 0) {
        if (quart == 0) atomicAdd(&g_acc[OFF_SBG + b], r1[0]);
        atomicAdd(&g_acc[OFF_SFG + b], r2[0]);
    }
}

// ---------------------------------------------------------------- lovasz (+ self-wipe + folded final)
// one block per (b,n); 1024 threads; CH=2 bins/thread; shfl-based prefix scan.
// Last block (ticket) combines all losses and writes out[0].
__global__ void __launch_bounds__(1024) k_lovasz(float* out) {
    int bn = blockIdx.x;       // b*16 + n
    int b = bn >> 4;
    unsigned* HF = g_hfg + (size_t)bn * NBINS;
    unsigned* HB = g_hbg + (size_t)bn * NBINS;
    const int CH = NBINS / 1024;  // 2
    int t = threadIdx.x;
    int lane = t & 31, warp = t >> 5;

    // load my bins (descending error order: rank r = t*CH+i, bin = NBINS-1-r)
    float fA[CH], bA[CH];
    float locF = 0.0f, locB = 0.0f;
#pragma unroll
    for (int i = 0; i < CH; i++) {
        int bin = NBINS - 1 - (t * CH + i);
        fA[i] = (float)HF[bin];
        bA[i] = (float)HB[bin];
        locF += fA[i];
        locB += bA[i];
        HF[bin] = 0u;     // self-wipe for next replay
        HB[bin] = 0u;
    }

    // warp-level inclusive scan of (locF, locB) in thread order
    float incF = locF, incB = locB;
#pragma unroll
    for (int d = 1; d < 32; d <<= 1) {
        float vF = __shfl_up_sync(0xffffffffu, incF, d);
        float vB = __shfl_up_sync(0xffffffffu, incB, d);
        if (lane >= d) { incF += vF; incB += vB; }
    }
    __shared__ float wF[32], wB[32];
    __shared__ float sred[1024];
    __shared__ int sMinR;
    if (t == 0) sMinR = NBINS;
    if (lane == 31) { wF[warp] = incF; wB[warp] = incB; }
    __syncthreads();
    float offF = 0.0f, offB = 0.0f, G = 0.0f;
#pragma unroll
    for (int w = 0; w < 32; w++) {
        float f = wF[w];
        if (w < warp) { offF += f; offB += wB[w]; }
        G += f;
    }
    float P = offF + incF - locF;   // exclusive prefix (fg)
    float Q = offB + incB - locB;   // exclusive prefix (bg)

    float contrib = 0.0f;
    if (G > 0.0f) {
#pragma unroll
        for (int i = 0; i < CH; i++) {
            float f = fA[i], bb = bA[i];
            if (f > 0.0f || bb > 0.0f) {
                int bin = NBINS - 1 - (t * CH + i);
                float e = ((float)bin + 0.5f) * (2.0f / NBINS);
                float gq = G + Q;
                float num = (G - P) * bb + f * gq;   // cancellation-free jacc delta
                float den = gq * (gq + bb);
                contrib += e * num / den;
                P += f;
                Q += bb;
            }
        }
    } else {  // degenerate: no fg voxels -> loss = max error present
#pragma unroll
        for (int i = 0; i < CH; i++) {
            if (fA[i] > 0.0f || bA[i] > 0.0f) {
                atomicMin(&sMinR, t * CH + i);
                break;
            }
        }
    }
    sred[t] = contrib;
    __syncthreads();
    for (int s2 = 512; s2 > 0; s2 >>= 1) {
        if (t < s2) sred[t] += sred[t + s2];
        __syncthreads();
    }
    if (t == 0) {
        float total = sred[0];
        if (G <= 0.0f && sMinR < NBINS)
            total = ((float)(NBINS - 1 - sMinR) + 0.5f) * (2.0f / NBINS);
        atomicAdd(&g_acc[OFF_ILOSS + b], total);
        __threadfence();
        unsigned tk = atomicAdd(&g_ticket, 1u);
        if (tk == (unsigned)(BB * NI - 1)) {        // last block: fold final
            volatile float* ga = g_acc;
            float r = 0.0f;
            for (int b2 = 0; b2 < BB; b2++) {
                float il = ga[OFF_ILOSS + b2] * (1.0f / NI);
                float vl = ga[OFF_VAR + b2];
                float sl = (ga[OFF_SBG + b2] + 10.0f * ga[OFF_SFG + b2]) * (1.0f / VV);
                r += il + 10.0f * vl + sl;
                ga[OFF_ILOSS + b2] = 0.0f;
                ga[OFF_VAR + b2] = 0.0f;
                ga[OFF_SBG + b2] = 0.0f;
                ga[OFF_SFG + b2] = 0.0f;
            }
            out[0] = r * (1.0f / BB);
            g_ticket = 0u;                           // reset for next replay
        }
    }
}

// ---------------------------------------------------------------- launch
extern "C" void kernel_launch(void* const* d_in, const int* in_sizes, int n_in,
                              void* d_out, int out_size) {
    const float* pred = (const float*)d_in[0];
    const int* inst = (const int*)d_in[1];
    const int* lab = (const int*)d_in[2];
    const int* cent = (const int*)d_in[3];

    {
        dim3 g(1024, BB);
        k_stats<<<g, 256>>>(pred, inst, cent);
    }
    k_params<<<1, 64>>>();
    k_nop<<<1, 1>>>();   // aligns ncu capture (-s 5) onto k_dist
    {
        dim3 g(DGRID, BB, 4);
        k_dist<<<g, 256>>>(pred, inst, lab);
    }
    k_lovasz<<<BB * NI, 1024>>>((float*)d_out);
}

// round 12
// speedup vs baseline: 1.5144x; 1.0398x over previous
#include <cuda_runtime.h>

#define BB 2
#define NCH 7
#define VV 2097152          // 32*256*256
#define NI 16
#define NSG 17
#define NBINS 2048
#define DGRID 92            // 92*2*4 = 736 blocks ~ single wave at 5 blocks/SM

// accumulator layout (floats)
#define OFF_CNT   0          // BB*NSG
#define OFF_SSUM  34         // BB*NSG*3
#define OFF_SSQ   136
#define OFF_XYZ   238
#define OFF_CCNT  340
#define OFF_CXYZ  374
#define OFF_VAR   476        // BB
#define OFF_SBG   478
#define OFF_SFG   480
#define OFF_ILOSS 482
#define OFF_S     484        // BB*NI*3  (NEGATED, pre-scaled by log2 e)
#define OFF_CEN   580        // BB*NI*3
#define ACC_N     676

__device__ float g_acc[ACC_N];                  // zero-init; self-cleaning
__device__ unsigned g_hfg[BB * NI * NBINS];     // 128KB fg counts
__device__ unsigned g_hbg[BB * NI * NBINS];     // 128KB bg counts
__device__ unsigned g_ticket;                   // lovasz completion ticket

__device__ __forceinline__ float fast_tanh(float x) {
    float r;
    asm("tanh.approx.f32 %0, %1;" : "=f"(r) : "f"(x));
    return r;
}
__device__ __forceinline__ float fast_ex2(float x) {
    float r;
    asm("ex2.approx.f32 %0, %1;" : "=f"(r) : "f"(x));
    return r;
}

// ---------------------------------------------------------------- stats
// Per-warp fixed-point packed accumulators (3 u64 per id), exact/bounded for
// exactly 256 voxels per warp. grid (1024, BB), 256 thr, 8 voxels/thread.
__global__ void __launch_bounds__(256) k_stats(const float* __restrict__ pred,
                                               const int* __restrict__ inst,
                                               const int* __restrict__ cent) {
    int b = blockIdx.y;
    __shared__ unsigned long long wacc[8][NSG][3];
    __shared__ float sm[NSG * 10];
    int tid = threadIdx.x;
    int warp = tid >> 5, lane = tid & 31;

    for (int j = tid; j < 8 * NSG * 3; j += 256)
        ((unsigned long long*)wacc)[j] = 0ull;
    for (int j = tid; j < NSG * 10; j += 256) sm[j] = 0.0f;
    __syncthreads();

    const float* sig = pred + ((size_t)b * NCH + 3) * VV;
    const int* ib = inst + (size_t)b * VV;
    const int* cb = cent + (size_t)b * VV;

    int v0 = (blockIdx.x * 256 + tid) * 8;
#pragma unroll
    for (int g = 0; g < 2; g++) {
        int vb = v0 + g * 4;
        float4 f0 = *(const float4*)(sig + vb);
        float4 f1 = *(const float4*)(sig + VV + vb);
        float4 f2 = *(const float4*)(sig + 2 * VV + vb);
        int4 iv = *(const int4*)(ib + vb);
        int4 cv = *(const int4*)(cb + vb);
        float a0[4] = {f0.x, f0.y, f0.z, f0.w};
        float a1[4] = {f1.x, f1.y, f1.z, f1.w};
        float a2[4] = {f2.x, f2.y, f2.z, f2.w};
        int ia[4] = {iv.x, iv.y, iv.z, iv.w};
        int ca[4] = {cv.x, cv.y, cv.z, cv.w};
#pragma unroll
        for (int k = 0; k < 4; k++) {
            int v = vb + k;
            int id = ia[k];
            float s0 = fminf(fmaxf(a0[k], -15.5f), 15.5f);
            float s1 = fminf(fmaxf(a1[k], -15.5f), 15.5f);
            float s2 = fminf(fmaxf(a2[k], -15.5f), 15.5f);
            unsigned xi = v & 255;
            unsigned yi = (v >> 8) & 255;
            unsigned zi = (unsigned)v >> 16;
            unsigned long long* base = wacc[warp][id];
            unsigned q0 = __float2uint_rn((s0 + 16.0f) * 256.0f);
            unsigned q1 = __float2uint_rn((s1 + 16.0f) * 256.0f);
            unsigned q2 = __float2uint_rn((s2 + 16.0f) * 256.0f);
            unsigned r0 = __float2uint_rn(s0 * s0 * 32.0f);
            unsigned r1 = __float2uint_rn(s1 * s1 * 32.0f);
            unsigned r2 = __float2uint_rn(s2 * s2 * 32.0f);
            atomicAdd(&base[0], (unsigned long long)xi
                                | ((unsigned long long)yi << 17)
                                | ((unsigned long long)zi << 34)
                                | (1ull << 48));
            atomicAdd(&base[1], (unsigned long long)q0
                                | ((unsigned long long)q1 << 21)
                                | ((unsigned long long)q2 << 42));
            atomicAdd(&base[2], (unsigned long long)r0
                                | ((unsigned long long)r1 << 21)
                                | ((unsigned long long)r2 << 42));
            if (ca[k] != 0) {   // centers are ~1-per-volume rare: direct global
                int bi = b * NSG + id;
                atomicAdd(&g_acc[OFF_CCNT + bi], 1.0f);
                atomicAdd(&g_acc[OFF_CXYZ + bi * 3 + 0], (float)xi * (1.0f / 1023.0f));
                atomicAdd(&g_acc[OFF_CXYZ + bi * 3 + 1], (float)yi * (1.0f / 1023.0f));
                atomicAdd(&g_acc[OFF_CXYZ + bi * 3 + 2], (float)zi * (1.0f / 31.0f));
            }
        }
    }
    __syncthreads();

    // decode per-warp packs -> block-level float accumulation
    if (lane < NSG) {
        unsigned long long pA = wacc[warp][lane][0];
        unsigned long long pB = wacc[warp][lane][1];
        unsigned long long pC = wacc[warp][lane][2];
        float cnt = (float)(unsigned)(pA >> 48);
        float xs = (float)(unsigned)(pA & 0x1FFFFu) * (1.0f / 1023.0f);
        float ys = (float)(unsigned)((pA >> 17) & 0x1FFFFu) * (1.0f / 1023.0f);
        float zs = (float)(unsigned)((pA >> 34) & 0x3FFFu) * (1.0f / 31.0f);
        float s0s = (float)(unsigned)(pB & 0x1FFFFFu) * (1.0f / 256.0f) - 16.0f * cnt;
        float s1s = (float)(unsigned)((pB >> 21) & 0x1FFFFFu) * (1.0f / 256.0f) - 16.0f * cnt;
        float s2s = (float)(unsigned)((pB >> 42) & 0x1FFFFFu) * (1.0f / 256.0f) - 16.0f * cnt;
        float r0s = (float)(unsigned)(pC & 0x1FFFFFu) * (1.0f / 32.0f);
        float r1s = (float)(unsigned)((pC >> 21) & 0x1FFFFFu) * (1.0f / 32.0f);
        float r2s = (float)(unsigned)((pC >> 42) & 0x1FFFFFu) * (1.0f / 32.0f);
        float* d = sm + lane * 10;
        atomicAdd(d + 0, cnt);
        atomicAdd(d + 1, s0s);
        atomicAdd(d + 2, s1s);
        atomicAdd(d + 3, s2s);
        atomicAdd(d + 4, r0s);
        atomicAdd(d + 5, r1s);
        atomicAdd(d + 6, r2s);
        atomicAdd(d + 7, xs);
        atomicAdd(d + 8, ys);
        atomicAdd(d + 9, zs);
    }
    __syncthreads();
    if (tid < NSG * 10) {
        int id = tid / 10, f = tid % 10;
        float vsm = sm[tid];
        if (vsm != 0.0f) {
            int bi = b * NSG + id;
            float* dst;
            if (f == 0)      dst = &g_acc[OFF_CNT  + bi];
            else if (f < 4)  dst = &g_acc[OFF_SSUM + bi * 3 + (f - 1)];
            else if (f < 7)  dst = &g_acc[OFF_SSQ  + bi * 3 + (f - 4)];
            else             dst = &g_acc[OFF_XYZ  + bi * 3 + (f - 7)];
            atomicAdd(dst, vsm);
        }
    }
}

// ---------------------------------------------------------------- params (+ zero stats accumulators)
__global__ void k_params() {
    int t = threadIdx.x;
    if (t >= BB * NSG) return;
    int b = t / NSG, id = t % NSG;
    float cnt = g_acc[OFF_CNT + t];
    float safe = fmaxf(cnt, 1.0f);
    float varsum = 0.0f;
    float m[3];
    float xyz[3], cxyz[3];
#pragma unroll
    for (int c = 0; c < 3; c++) {
        float ss = g_acc[OFF_SSUM + t * 3 + c];
        float sq = g_acc[OFF_SSQ + t * 3 + c];
        float mm = ss / safe;
        m[c] = mm;
        varsum += (sq - 2.0f * mm * ss + cnt * mm * mm) / safe;
        xyz[c] = g_acc[OFF_XYZ + t * 3 + c];
        cxyz[c] = g_acc[OFF_CXYZ + t * 3 + c];
    }
    float ccnt = g_acc[OFF_CCNT + t];
    // zero for next graph replay
    g_acc[OFF_CNT + t] = 0.0f;
    g_acc[OFF_CCNT + t] = 0.0f;
#pragma unroll
    for (int c = 0; c < 3; c++) {
        g_acc[OFF_SSUM + t * 3 + c] = 0.0f;
        g_acc[OFF_SSQ + t * 3 + c] = 0.0f;
        g_acc[OFF_XYZ + t * 3 + c] = 0.0f;
        g_acc[OFF_CXYZ + t * 3 + c] = 0.0f;
    }
    if (id >= 1) {
        atomicAdd(&g_acc[OFF_VAR + b], varsum * (1.0f / (3.0f * NI)));
        bool one = (ccnt == 1.0f);
        int p = (b * NI + (id - 1)) * 3;
#pragma unroll
        for (int c = 0; c < 3; c++) {
            float cen = one ? cxyz[c] : xyz[c] / safe;
            g_acc[OFF_CEN + p + c] = cen;
            // NEGATED + pre-scaled by log2(e): k_dist computes d = ex2(sum)
            g_acc[OFF_S + p + c] = -expf(10.0f * m[c]) * 1.4426950408889634f;
        }
    }
}

// ---------------------------------------------------------------- nop (profiler alignment: puts k_dist at capture index 5)
__global__ void k_nop() {}

// ---------------------------------------------------------------- dist + SMEM histogram + seed loss
// grid (DGRID, BB, 4) = 736 blocks, single wave at 5 blocks/SM (reg cap 51).
// Params live in (volatile) smem: trades 24 loop-invariant registers for
// pipelined LDS so the 5-block occupancy target is met without hot spills.
// Unified u16-packed smem hist: regions [0..3]=bg, [4..7]=fg (32KB); max
// per-(block,inst,bin) count <= 23040 < 65535, no overflow.
__global__ void __launch_bounds__(256, 5) k_dist(const float* __restrict__ pred,
                                                 const int* __restrict__ inst,
                                                 const int* __restrict__ lab) {
    __shared__ unsigned shist[8 * NBINS / 2];     // 32KB
    __shared__ float spar[24];                    // 4 inst x (s0,s1,s2,c0,c1,c2)
    __shared__ float r1[256], r2[256];
    int b = blockIdx.y;
    int quart = blockIdx.z;          // instances [quart*4, quart*4+4)
    int nbase = quart * 4;

    if (threadIdx.x < 24) {
        int j = threadIdx.x / 6, c = threadIdx.x % 6;
        int p = (b * NI + nbase + j) * 3;
        spar[threadIdx.x] = (c < 3) ? g_acc[OFF_S + p + c]
                                    : g_acc[OFF_CEN + p + (c - 3)];
    }
    for (int i = threadIdx.x; i < 8 * NBINS / 2; i += 256) shist[i] = 0u;
    __syncthreads();
    volatile float* vp = spar;       // force LDS per use (keeps regs <= 51)

    const float* pb = pred + (size_t)b * NCH * VV;
    const int* ib = inst + (size_t)b * VV;
    const int* lb = lab + (size_t)b * VV;

    float accbg = 0.0f, accfg = 0.0f;

    for (int v = blockIdx.x * 256 + threadIdx.x; v < VV; v += DGRID * 256) {
        float x = (float)(v & 255) * (1.0f / 1023.0f);
        float y = (float)((v >> 8) & 255) * (1.0f / 1023.0f);
        float z = (float)(v >> 16) * (1.0f / 31.0f);
        float e0 = fast_tanh(pb[v]) + x;
        float e1 = fast_tanh(pb[VV + v]) + y;
        float e2 = fast_tanh(pb[2 * VV + v]) + z;
        int id = ib[v];
        float down = 0.0f;
#pragma unroll
        for (int j = 0; j < 4; j++) {
            float S0 = vp[j * 6 + 0], S1 = vp[j * 6 + 1], S2 = vp[j * 6 + 2];
            float C0 = vp[j * 6 + 3], C1 = vp[j * 6 + 4], C2 = vp[j * 6 + 5];
            float dx = e0 - C0, dy = e1 - C1, dz = e2 - C2;
            float arg = S0 * dx * dx + S1 * dy * dy + S2 * dz * dz;
            float d = fast_ex2(arg);                // S already negative*log2e
            int fg = (id == nbase + j + 1) ? 1 : 0;
            if (fg) down = d;
            // shared bin base: it = floor(d*NBINS); bg bin = it, fg bin = NBINS-1-it
            int it = (int)(d * (float)NBINS);
            it = min(it, NBINS - 1);
            int bin = fg ? (NBINS - 1 - it) : it;
            unsigned addv = 1u << ((bin & 1) << 4);
            atomicAdd(&shist[((j + (fg << 2)) << 10) | (bin >> 1)], addv);
        }
        bool own = (id > nbase && id <= nbase + 4);
        bool bg = (quart == 0) && (lb[v] == 0);
        if (own | bg) {
            float sd = 1.0f / (1.0f + __expf(-pb[6 * VV + v]));
            if (own) {
                float t = sd - down;
                accfg += t * t;
            }
            if (bg) accbg += sd * sd;
        }
    }

    __syncthreads();
    // flush: decode u16 halves, pre-aggregated REDs to global fg/bg hists
    for (int i = threadIdx.x; i < 8 * NBINS / 2; i += 256) {
        unsigned c = shist[i];
        int region = i >> 10;             // 0..7
        int j = region & 3;
        unsigned* dst = (region & 4) ? g_hfg : g_hbg;
        dst += (size_t)(b * NI + nbase + j) * NBINS;
        int w = i & 1023;                 // word -> bins 2w, 2w+1
        unsigned lo = c & 0xFFFFu, hi = c >> 16;
        if (lo) atomicAdd(&dst[2 * w], lo);
        if (hi) atomicAdd(&dst[2 * w + 1], hi);
    }

    int t = threadIdx.x;
    r1[t] = accbg;
    r2[t] = accfg;
    __syncthreads();
    for (int s = 128; s > 0; s >>= 1) {
        if (t < s) { r1[t] += r1[t + s]; r2[t] += r2[t + s]; }
        __syncthreads();
    }
    if (t == 0) {
        if (quart == 0) atomicAdd(&g_acc[OFF_SBG + b], r1[0]);
        atomicAdd(&g_acc[OFF_SFG + b], r2[0]);
    }
}

// ---------------------------------------------------------------- lovasz (+ self-wipe + folded final)
// one block per (b,n); 1024 threads; CH=2 bins/thread; shfl-based prefix scan.
// Last block (ticket) combines all losses and writes out[0].
__global__ void __launch_bounds__(1024) k_lovasz(float* out) {
    int bn = blockIdx.x;       // b*16 + n
    int b = bn >> 4;
    unsigned* HF = g_hfg + (size_t)bn * NBINS;
    unsigned* HB = g_hbg + (size_t)bn * NBINS;
    const int CH = NBINS / 1024;  // 2
    int t = threadIdx.x;
    int lane = t & 31, warp = t >> 5;

    // load my bins (descending error order: rank r = t*CH+i, bin = NBINS-1-r)
    float fA[CH], bA[CH];
    float locF = 0.0f, locB = 0.0f;
#pragma unroll
    for (int i = 0; i < CH; i++) {
        int bin = NBINS - 1 - (t * CH + i);
        fA[i] = (float)HF[bin];
        bA[i] = (float)HB[bin];
        locF += fA[i];
        locB += bA[i];
        HF[bin] = 0u;     // self-wipe for next replay
        HB[bin] = 0u;
    }

    // warp-level inclusive scan of (locF, locB) in thread order
    float incF = locF, incB = locB;
#pragma unroll
    for (int d = 1; d < 32; d <<= 1) {
        float vF = __shfl_up_sync(0xffffffffu, incF, d);
        float vB = __shfl_up_sync(0xffffffffu, incB, d);
        if (lane >= d) { incF += vF; incB += vB; }
    }
    __shared__ float wF[32], wB[32];
    __shared__ float sred[1024];
    __shared__ int sMinR;
    if (t == 0) sMinR = NBINS;
    if (lane == 31) { wF[warp] = incF; wB[warp] = incB; }
    __syncthreads();
    float offF = 0.0f, offB = 0.0f, G = 0.0f;
#pragma unroll
    for (int w = 0; w < 32; w++) {
        float f = wF[w];
        if (w < warp) { offF += f; offB += wB[w]; }
        G += f;
    }
    float P = offF + incF - locF;   // exclusive prefix (fg)
    float Q = offB + incB - locB;   // exclusive prefix (bg)

    float contrib = 0.0f;
    if (G > 0.0f) {
#pragma unroll
        for (int i = 0; i < CH; i++) {
            float f = fA[i], bb = bA[i];
            if (f > 0.0f || bb > 0.0f) {
                int bin = NBINS - 1 - (t * CH + i);
                float e = ((float)bin + 0.5f) * (2.0f / NBINS);
                float gq = G + Q;
                float num = (G - P) * bb + f * gq;   // cancellation-free jacc delta
                float den = gq * (gq + bb);
                contrib += e * num / den;
                P += f;
                Q += bb;
            }
        }
    } else {  // degenerate: no fg voxels -> loss = max error present
#pragma unroll
        for (int i = 0; i < CH; i++) {
            if (fA[i] > 0.0f || bA[i] > 0.0f) {
                atomicMin(&sMinR, t * CH + i);
                break;
            }
        }
    }
    sred[t] = contrib;
    __syncthreads();
    for (int s2 = 512; s2 > 0; s2 >>= 1) {
        if (t < s2) sred[t] += sred[t + s2];
        __syncthreads();
    }
    if (t == 0) {
        float total = sred[0];
        if (G <= 0.0f && sMinR < NBINS)
            total = ((float)(NBINS - 1 - sMinR) + 0.5f) * (2.0f / NBINS);
        atomicAdd(&g_acc[OFF_ILOSS + b], total);
        __threadfence();
        unsigned tk = atomicAdd(&g_ticket, 1u);
        if (tk == (unsigned)(BB * NI - 1)) {        // last block: fold final
            volatile float* ga = g_acc;
            float r = 0.0f;
            for (int b2 = 0; b2 < BB; b2++) {
                float il = ga[OFF_ILOSS + b2] * (1.0f / NI);
                float vl = ga[OFF_VAR + b2];
                float sl = (ga[OFF_SBG + b2] + 10.0f * ga[OFF_SFG + b2]) * (1.0f / VV);
                r += il + 10.0f * vl + sl;
                ga[OFF_ILOSS + b2] = 0.0f;
                ga[OFF_VAR + b2] = 0.0f;
                ga[OFF_SBG + b2] = 0.0f;
                ga[OFF_SFG + b2] = 0.0f;
            }
            out[0] = r * (1.0f / BB);
            g_ticket = 0u;                           // reset for next replay
        }
    }
}

// ---------------------------------------------------------------- launch
extern "C" void kernel_launch(void* const* d_in, const int* in_sizes, int n_in,
                              void* d_out, int out_size) {
    const float* pred = (const float*)d_in[0];
    const int* inst = (const int*)d_in[1];
    const int* lab = (const int*)d_in[2];
    const int* cent = (const int*)d_in[3];

    {
        dim3 g(1024, BB);
        k_stats<<<g, 256>>>(pred, inst, cent);
    }
    k_params<<<1, 64>>>();
    k_nop<<<1, 1>>>();   // aligns ncu capture (-s 5) onto k_dist
    {
        dim3 g(DGRID, BB, 4);
        k_dist<<<g, 256>>>(pred, inst, lab);
    }
    k_lovasz<<<BB * NI, 1024>>>((float*)d_out);
}

// round 13
// speedup vs baseline: 1.5846x; 1.0463x over previous
#include <cuda_runtime.h>

#define BB 2
#define NCH 7
#define VV 2097152          // 32*256*256
#define NI 16
#define NSG 17
#define NBINS 2048
#define DGRID 111           // 111*2*4 = 888 blocks = exactly 6/SM * 148 SMs

// accumulator layout (floats)
#define OFF_CNT   0          // BB*NSG
#define OFF_SSUM  34         // BB*NSG*3
#define OFF_SSQ   136
#define OFF_XYZ   238
#define OFF_CCNT  340
#define OFF_CXYZ  374
#define OFF_VAR   476        // BB
#define OFF_SBG   478
#define OFF_SFG   480
#define OFF_ILOSS 482
#define OFF_S     484        // BB*NI*3  (NEGATED, pre-scaled by log2 e)
#define OFF_CEN   580        // BB*NI*3
#define ACC_N     676

__device__ float g_acc[ACC_N];                  // zero-init; self-cleaning
__device__ unsigned g_hfg[BB * NI * NBINS];     // 128KB fg counts
__device__ unsigned g_hbg[BB * NI * NBINS];     // 128KB bg counts
__device__ unsigned g_ticket;                   // lovasz completion ticket

__device__ __forceinline__ float fast_tanh(float x) {
    float r;
    asm("tanh.approx.f32 %0, %1;" : "=f"(r) : "f"(x));
    return r;
}
__device__ __forceinline__ float fast_ex2(float x) {
    float r;
    asm("ex2.approx.f32 %0, %1;" : "=f"(r) : "f"(x));
    return r;
}

// ---------------------------------------------------------------- stats
// Per-warp fixed-point packed accumulators (3 u64 per id), exact/bounded for
// exactly 256 voxels per warp. grid (1024, BB), 256 thr, 8 voxels/thread.
__global__ void __launch_bounds__(256) k_stats(const float* __restrict__ pred,
                                               const int* __restrict__ inst,
                                               const int* __restrict__ cent) {
    int b = blockIdx.y;
    __shared__ unsigned long long wacc[8][NSG][3];
    __shared__ float sm[NSG * 10];
    int tid = threadIdx.x;
    int warp = tid >> 5, lane = tid & 31;

    for (int j = tid; j < 8 * NSG * 3; j += 256)
        ((unsigned long long*)wacc)[j] = 0ull;
    for (int j = tid; j < NSG * 10; j += 256) sm[j] = 0.0f;
    __syncthreads();

    const float* sig = pred + ((size_t)b * NCH + 3) * VV;
    const int* ib = inst + (size_t)b * VV;
    const int* cb = cent + (size_t)b * VV;

    int v0 = (blockIdx.x * 256 + tid) * 8;
#pragma unroll
    for (int g = 0; g < 2; g++) {
        int vb = v0 + g * 4;
        float4 f0 = *(const float4*)(sig + vb);
        float4 f1 = *(const float4*)(sig + VV + vb);
        float4 f2 = *(const float4*)(sig + 2 * VV + vb);
        int4 iv = *(const int4*)(ib + vb);
        int4 cv = *(const int4*)(cb + vb);
        float a0[4] = {f0.x, f0.y, f0.z, f0.w};
        float a1[4] = {f1.x, f1.y, f1.z, f1.w};
        float a2[4] = {f2.x, f2.y, f2.z, f2.w};
        int ia[4] = {iv.x, iv.y, iv.z, iv.w};
        int ca[4] = {cv.x, cv.y, cv.z, cv.w};
#pragma unroll
        for (int k = 0; k < 4; k++) {
            int v = vb + k;
            int id = ia[k];
            float s0 = fminf(fmaxf(a0[k], -15.5f), 15.5f);
            float s1 = fminf(fmaxf(a1[k], -15.5f), 15.5f);
            float s2 = fminf(fmaxf(a2[k], -15.5f), 15.5f);
            unsigned xi = v & 255;
            unsigned yi = (v >> 8) & 255;
            unsigned zi = (unsigned)v >> 16;
            unsigned long long* base = wacc[warp][id];
            unsigned q0 = __float2uint_rn((s0 + 16.0f) * 256.0f);
            unsigned q1 = __float2uint_rn((s1 + 16.0f) * 256.0f);
            unsigned q2 = __float2uint_rn((s2 + 16.0f) * 256.0f);
            unsigned r0 = __float2uint_rn(s0 * s0 * 32.0f);
            unsigned r1 = __float2uint_rn(s1 * s1 * 32.0f);
            unsigned r2 = __float2uint_rn(s2 * s2 * 32.0f);
            atomicAdd(&base[0], (unsigned long long)xi
                                | ((unsigned long long)yi << 17)
                                | ((unsigned long long)zi << 34)
                                | (1ull << 48));
            atomicAdd(&base[1], (unsigned long long)q0
                                | ((unsigned long long)q1 << 21)
                                | ((unsigned long long)q2 << 42));
            atomicAdd(&base[2], (unsigned long long)r0
                                | ((unsigned long long)r1 << 21)
                                | ((unsigned long long)r2 << 42));
            if (ca[k] != 0) {   // centers are ~1-per-volume rare: direct global
                int bi = b * NSG + id;
                atomicAdd(&g_acc[OFF_CCNT + bi], 1.0f);
                atomicAdd(&g_acc[OFF_CXYZ + bi * 3 + 0], (float)xi * (1.0f / 1023.0f));
                atomicAdd(&g_acc[OFF_CXYZ + bi * 3 + 1], (float)yi * (1.0f / 1023.0f));
                atomicAdd(&g_acc[OFF_CXYZ + bi * 3 + 2], (float)zi * (1.0f / 31.0f));
            }
        }
    }
    __syncthreads();

    // decode per-warp packs -> block-level float accumulation
    if (lane < NSG) {
        unsigned long long pA = wacc[warp][lane][0];
        unsigned long long pB = wacc[warp][lane][1];
        unsigned long long pC = wacc[warp][lane][2];
        float cnt = (float)(unsigned)(pA >> 48);
        float xs = (float)(unsigned)(pA & 0x1FFFFu) * (1.0f / 1023.0f);
        float ys = (float)(unsigned)((pA >> 17) & 0x1FFFFu) * (1.0f / 1023.0f);
        float zs = (float)(unsigned)((pA >> 34) & 0x3FFFu) * (1.0f / 31.0f);
        float s0s = (float)(unsigned)(pB & 0x1FFFFFu) * (1.0f / 256.0f) - 16.0f * cnt;
        float s1s = (float)(unsigned)((pB >> 21) & 0x1FFFFFu) * (1.0f / 256.0f) - 16.0f * cnt;
        float s2s = (float)(unsigned)((pB >> 42) & 0x1FFFFFu) * (1.0f / 256.0f) - 16.0f * cnt;
        float r0s = (float)(unsigned)(pC & 0x1FFFFFu) * (1.0f / 32.0f);
        float r1s = (float)(unsigned)((pC >> 21) & 0x1FFFFFu) * (1.0f / 32.0f);
        float r2s = (float)(unsigned)((pC >> 42) & 0x1FFFFFu) * (1.0f / 32.0f);
        float* d = sm + lane * 10;
        atomicAdd(d + 0, cnt);
        atomicAdd(d + 1, s0s);
        atomicAdd(d + 2, s1s);
        atomicAdd(d + 3, s2s);
        atomicAdd(d + 4, r0s);
        atomicAdd(d + 5, r1s);
        atomicAdd(d + 6, r2s);
        atomicAdd(d + 7, xs);
        atomicAdd(d + 8, ys);
        atomicAdd(d + 9, zs);
    }
    __syncthreads();
    if (tid < NSG * 10) {
        int id = tid / 10, f = tid % 10;
        float vsm = sm[tid];
        if (vsm != 0.0f) {
            int bi = b * NSG + id;
            float* dst;
            if (f == 0)      dst = &g_acc[OFF_CNT  + bi];
            else if (f < 4)  dst = &g_acc[OFF_SSUM + bi * 3 + (f - 1)];
            else if (f < 7)  dst = &g_acc[OFF_SSQ  + bi * 3 + (f - 4)];
            else             dst = &g_acc[OFF_XYZ  + bi * 3 + (f - 7)];
            atomicAdd(dst, vsm);
        }
    }
}

// ---------------------------------------------------------------- params (+ zero stats accumulators)
__global__ void k_params() {
    int t = threadIdx.x;
    if (t >= BB * NSG) return;
    int b = t / NSG, id = t % NSG;
    float cnt = g_acc[OFF_CNT + t];
    float safe = fmaxf(cnt, 1.0f);
    float varsum = 0.0f;
    float m[3];
    float xyz[3], cxyz[3];
#pragma unroll
    for (int c = 0; c < 3; c++) {
        float ss = g_acc[OFF_SSUM + t * 3 + c];
        float sq = g_acc[OFF_SSQ + t * 3 + c];
        float mm = ss / safe;
        m[c] = mm;
        varsum += (sq - 2.0f * mm * ss + cnt * mm * mm) / safe;
        xyz[c] = g_acc[OFF_XYZ + t * 3 + c];
        cxyz[c] = g_acc[OFF_CXYZ + t * 3 + c];
    }
    float ccnt = g_acc[OFF_CCNT + t];
    // zero for next graph replay
    g_acc[OFF_CNT + t] = 0.0f;
    g_acc[OFF_CCNT + t] = 0.0f;
#pragma unroll
    for (int c = 0; c < 3; c++) {
        g_acc[OFF_SSUM + t * 3 + c] = 0.0f;
        g_acc[OFF_SSQ + t * 3 + c] = 0.0f;
        g_acc[OFF_XYZ + t * 3 + c] = 0.0f;
        g_acc[OFF_CXYZ + t * 3 + c] = 0.0f;
    }
    if (id >= 1) {
        atomicAdd(&g_acc[OFF_VAR + b], varsum * (1.0f / (3.0f * NI)));
        bool one = (ccnt == 1.0f);
        int p = (b * NI + (id - 1)) * 3;
#pragma unroll
        for (int c = 0; c < 3; c++) {
            float cen = one ? cxyz[c] : xyz[c] / safe;
            g_acc[OFF_CEN + p + c] = cen;
            // NEGATED + pre-scaled by log2(e): k_dist computes d = ex2(sum)
            g_acc[OFF_S + p + c] = -expf(10.0f * m[c]) * 1.4426950408889634f;
        }
    }
}

// ---------------------------------------------------------------- nop (profiler alignment: puts k_dist at capture index 5)
__global__ void k_nop() {}

// ---------------------------------------------------------------- dist + SMEM histogram + seed loss
// grid (DGRID, BB, 4) = 888 blocks, single wave at 6 blocks/SM (reg cap 42;
// last build used 40). Params in volatile smem (saves 24 loop-invariant regs).
// Unified u16-packed smem hist: regions [0..3]=bg, [4..7]=fg (32KB); max
// per-(block,inst,bin) count <= 18944 < 65535, no overflow.
__global__ void __launch_bounds__(256, 6) k_dist(const float* __restrict__ pred,
                                                 const int* __restrict__ inst,
                                                 const int* __restrict__ lab) {
    __shared__ unsigned shist[8 * NBINS / 2];     // 32KB
    __shared__ float spar[24];                    // 4 inst x (s0,s1,s2,c0,c1,c2)
    __shared__ float r1[256], r2[256];
    int b = blockIdx.y;
    int quart = blockIdx.z;          // instances [quart*4, quart*4+4)
    int nbase = quart * 4;

    if (threadIdx.x < 24) {
        int j = threadIdx.x / 6, c = threadIdx.x % 6;
        int p = (b * NI + nbase + j) * 3;
        spar[threadIdx.x] = (c < 3) ? g_acc[OFF_S + p + c]
                                    : g_acc[OFF_CEN + p + (c - 3)];
    }
    for (int i = threadIdx.x; i < 8 * NBINS / 2; i += 256) shist[i] = 0u;
    __syncthreads();
    volatile float* vp = spar;       // force LDS per use (keeps regs low)

    const float* pb = pred + (size_t)b * NCH * VV;
    const int* ib = inst + (size_t)b * VV;
    const int* lb = lab + (size_t)b * VV;

    float accbg = 0.0f, accfg = 0.0f;

    for (int v = blockIdx.x * 256 + threadIdx.x; v < VV; v += DGRID * 256) {
        float x = (float)(v & 255) * (1.0f / 1023.0f);
        float y = (float)((v >> 8) & 255) * (1.0f / 1023.0f);
        float z = (float)(v >> 16) * (1.0f / 31.0f);
        float e0 = fast_tanh(pb[v]) + x;
        float e1 = fast_tanh(pb[VV + v]) + y;
        float e2 = fast_tanh(pb[2 * VV + v]) + z;
        int id = ib[v];
        float down = 0.0f;
#pragma unroll
        for (int j = 0; j < 4; j++) {
            float S0 = vp[j * 6 + 0], S1 = vp[j * 6 + 1], S2 = vp[j * 6 + 2];
            float C0 = vp[j * 6 + 3], C1 = vp[j * 6 + 4], C2 = vp[j * 6 + 5];
            float dx = e0 - C0, dy = e1 - C1, dz = e2 - C2;
            float arg = S0 * dx * dx + S1 * dy * dy + S2 * dz * dz;
            float d = fast_ex2(arg);                // S already negative*log2e
            int fg = (id == nbase + j + 1) ? 1 : 0;
            if (fg) down = d;
            // shared bin base: it = floor(d*NBINS); bg bin = it, fg bin = NBINS-1-it
            int it = (int)(d * (float)NBINS);
            it = min(it, NBINS - 1);
            int bin = fg ? (NBINS - 1 - it) : it;
            unsigned addv = 1u << ((bin & 1) << 4);
            atomicAdd(&shist[((j + (fg << 2)) << 10) | (bin >> 1)], addv);
        }
        bool own = (id > nbase && id <= nbase + 4);
        bool bg = (quart == 0) && (lb[v] == 0);
        if (own | bg) {
            float sd = 1.0f / (1.0f + __expf(-pb[6 * VV + v]));
            if (own) {
                float t = sd - down;
                accfg += t * t;
            }
            if (bg) accbg += sd * sd;
        }
    }

    __syncthreads();
    // flush: decode u16 halves, pre-aggregated REDs to global fg/bg hists
    for (int i = threadIdx.x; i < 8 * NBINS / 2; i += 256) {
        unsigned c = shist[i];
        int region = i >> 10;             // 0..7
        int j = region & 3;
        unsigned* dst = (region & 4) ? g_hfg : g_hbg;
        dst += (size_t)(b * NI + nbase + j) * NBINS;
        int w = i & 1023;                 // word -> bins 2w, 2w+1
        unsigned lo = c & 0xFFFFu, hi = c >> 16;
        if (lo) atomicAdd(&dst[2 * w], lo);
        if (hi) atomicAdd(&dst[2 * w + 1], hi);
    }

    int t = threadIdx.x;
    r1[t] = accbg;
    r2[t] = accfg;
    __syncthreads();
    for (int s = 128; s > 0; s >>= 1) {
        if (t < s) { r1[t] += r1[t + s]; r2[t] += r2[t + s]; }
        __syncthreads();
    }
    if (t == 0) {
        if (quart == 0) atomicAdd(&g_acc[OFF_SBG + b], r1[0]);
        atomicAdd(&g_acc[OFF_SFG + b], r2[0]);
    }
}

// ---------------------------------------------------------------- lovasz (+ self-wipe + folded final)
// one block per (b,n); 1024 threads; CH=2 bins/thread; shfl-based prefix scan.
// Last block (ticket) combines all losses and writes out[0].
__global__ void __launch_bounds__(1024) k_lovasz(float* out) {
    int bn = blockIdx.x;       // b*16 + n
    int b = bn >> 4;
    unsigned* HF = g_hfg + (size_t)bn * NBINS;
    unsigned* HB = g_hbg + (size_t)bn * NBINS;
    const int CH = NBINS / 1024;  // 2
    int t = threadIdx.x;
    int lane = t & 31, warp = t >> 5;

    // load my bins (descending error order: rank r = t*CH+i, bin = NBINS-1-r)
    float fA[CH], bA[CH];
    float locF = 0.0f, locB = 0.0f;
#pragma unroll
    for (int i = 0; i < CH; i++) {
        int bin = NBINS - 1 - (t * CH + i);
        fA[i] = (float)HF[bin];
        bA[i] = (float)HB[bin];
        locF += fA[i];
        locB += bA[i];
        HF[bin] = 0u;     // self-wipe for next replay
        HB[bin] = 0u;
    }

    // warp-level inclusive scan of (locF, locB) in thread order
    float incF = locF, incB = locB;
#pragma unroll
    for (int d = 1; d < 32; d <<= 1) {
        float vF = __shfl_up_sync(0xffffffffu, incF, d);
        float vB = __shfl_up_sync(0xffffffffu, incB, d);
        if (lane >= d) { incF += vF; incB += vB; }
    }
    __shared__ float wF[32], wB[32];
    __shared__ float sred[1024];
    __shared__ int sMinR;
    if (t == 0) sMinR = NBINS;
    if (lane == 31) { wF[warp] = incF; wB[warp] = incB; }
    __syncthreads();
    float offF = 0.0f, offB = 0.0f, G = 0.0f;
#pragma unroll
    for (int w = 0; w < 32; w++) {
        float f = wF[w];
        if (w < warp) { offF += f; offB += wB[w]; }
        G += f;
    }
    float P = offF + incF - locF;   // exclusive prefix (fg)
    float Q = offB + incB - locB;   // exclusive prefix (bg)

    float contrib = 0.0f;
    if (G > 0.0f) {
#pragma unroll
        for (int i = 0; i < CH; i++) {
            float f = fA[i], bb = bA[i];
            if (f > 0.0f || bb > 0.0f) {
                int bin = NBINS - 1 - (t * CH + i);
                float e = ((float)bin + 0.5f) * (2.0f / NBINS);
                float gq = G + Q;
                float num = (G - P) * bb + f * gq;   // cancellation-free jacc delta
                float den = gq * (gq + bb);
                contrib += e * num / den;
                P += f;
                Q += bb;
            }
        }
    } else {  // degenerate: no fg voxels -> loss = max error present
#pragma unroll
        for (int i = 0; i < CH; i++) {
            if (fA[i] > 0.0f || bA[i] > 0.0f) {
                atomicMin(&sMinR, t * CH + i);
                break;
            }
        }
    }
    sred[t] = contrib;
    __syncthreads();
    for (int s2 = 512; s2 > 0; s2 >>= 1) {
        if (t < s2) sred[t] += sred[t + s2];
        __syncthreads();
    }
    if (t == 0) {
        float total = sred[0];
        if (G <= 0.0f && sMinR < NBINS)
            total = ((float)(NBINS - 1 - sMinR) + 0.5f) * (2.0f / NBINS);
        atomicAdd(&g_acc[OFF_ILOSS + b], total);
        __threadfence();
        unsigned tk = atomicAdd(&g_ticket, 1u);
        if (tk == (unsigned)(BB * NI - 1)) {        // last block: fold final
            volatile float* ga = g_acc;
            float r = 0.0f;
            for (int b2 = 0; b2 < BB; b2++) {
                float il = ga[OFF_ILOSS + b2] * (1.0f / NI);
                float vl = ga[OFF_VAR + b2];
                float sl = (ga[OFF_SBG + b2] + 10.0f * ga[OFF_SFG + b2]) * (1.0f / VV);
                r += il + 10.0f * vl + sl;
                ga[OFF_ILOSS + b2] = 0.0f;
                ga[OFF_VAR + b2] = 0.0f;
                ga[OFF_SBG + b2] = 0.0f;
                ga[OFF_SFG + b2] = 0.0f;
            }
            out[0] = r * (1.0f / BB);
            g_ticket = 0u;                           // reset for next replay
        }
    }
}

// ---------------------------------------------------------------- launch
extern "C" void kernel_launch(void* const* d_in, const int* in_sizes, int n_in,
                              void* d_out, int out_size) {
    const float* pred = (const float*)d_in[0];
    const int* inst = (const int*)d_in[1];
    const int* lab = (const int*)d_in[2];
    const int* cent = (const int*)d_in[3];

    {
        dim3 g(1024, BB);
        k_stats<<<g, 256>>>(pred, inst, cent);
    }
    k_params<<<1, 64>>>();
    k_nop<<<1, 1>>>();   // aligns ncu capture (-s 5) onto k_dist
    {
        dim3 g(DGRID, BB, 4);
        k_dist<<<g, 256>>>(pred, inst, lab);
    }
    k_lovasz<<<BB * NI, 1024>>>((float*)d_out);
}

// round 14
// speedup vs baseline: 1.6108x; 1.0166x over previous
#include <cuda_runtime.h>

#define BB 2
#define NCH 7
#define VV 2097152          // 32*256*256
#define NI 16
#define NSG 17
#define NBINS 2048
#define DGRID 111           // 111*2*4 = 888 blocks = exactly 6/SM * 148 SMs

// accumulator layout (floats)
#define OFF_CNT   0          // BB*NSG
#define OFF_SSUM  34         // BB*NSG*3
#define OFF_SSQ   136
#define OFF_XYZ   238
#define OFF_CCNT  340
#define OFF_CXYZ  374
#define OFF_VAR   476        // BB
#define OFF_SBG   478
#define OFF_SFG   480
#define OFF_ILOSS 482
#define OFF_S     484        // BB*NI*3  (NEGATED, pre-scaled by log2 e)
#define OFF_CEN   580        // BB*NI*3
#define ACC_N     676

__device__ float g_acc[ACC_N];                  // zero-init; self-cleaning
__device__ unsigned g_hfg[BB * NI * NBINS];     // 128KB fg counts
__device__ unsigned g_hbg[BB * NI * NBINS];     // 128KB bg counts
__device__ unsigned g_ticket;                   // lovasz completion ticket

__device__ __forceinline__ float fast_tanh(float x) {
    float r;
    asm("tanh.approx.f32 %0, %1;" : "=f"(r) : "f"(x));
    return r;
}
__device__ __forceinline__ float fast_ex2(float x) {
    float r;
    asm("ex2.approx.f32 %0, %1;" : "=f"(r) : "f"(x));
    return r;
}
__device__ __forceinline__ unsigned smem_u32(const void* p) {
    unsigned a;
    asm("{ .reg .u64 t; cvta.to.shared.u64 t, %1; cvt.u32.u64 %0, t; }"
        : "=r"(a) : "l"(p));
    return a;
}
__device__ __forceinline__ void lds_v4(float& a, float& b, float& c, float& d,
                                       unsigned addr) {
    asm volatile("ld.shared.v4.f32 {%0,%1,%2,%3}, [%4];"
                 : "=f"(a), "=f"(b), "=f"(c), "=f"(d) : "r"(addr));
}
__device__ __forceinline__ void lds_v2(float& a, float& b, unsigned addr) {
    asm volatile("ld.shared.v2.f32 {%0,%1}, [%2];"
                 : "=f"(a), "=f"(b) : "r"(addr));
}

// ---------------------------------------------------------------- stats
// Per-warp fixed-point packed accumulators (3 u64 per id), exact/bounded for
// exactly 256 voxels per warp. grid (1024, BB), 256 thr, 8 voxels/thread.
__global__ void __launch_bounds__(256) k_stats(const float* __restrict__ pred,
                                               const int* __restrict__ inst,
                                               const int* __restrict__ cent) {
    int b = blockIdx.y;
    __shared__ unsigned long long wacc[8][NSG][3];
    __shared__ float sm[NSG * 10];
    int tid = threadIdx.x;
    int warp = tid >> 5, lane = tid & 31;

    for (int j = tid; j < 8 * NSG * 3; j += 256)
        ((unsigned long long*)wacc)[j] = 0ull;
    for (int j = tid; j < NSG * 10; j += 256) sm[j] = 0.0f;
    __syncthreads();

    const float* sig = pred + ((size_t)b * NCH + 3) * VV;
    const int* ib = inst + (size_t)b * VV;
    const int* cb = cent + (size_t)b * VV;

    int v0 = (blockIdx.x * 256 + tid) * 8;
#pragma unroll
    for (int g = 0; g < 2; g++) {
        int vb = v0 + g * 4;
        float4 f0 = *(const float4*)(sig + vb);
        float4 f1 = *(const float4*)(sig + VV + vb);
        float4 f2 = *(const float4*)(sig + 2 * VV + vb);
        int4 iv = *(const int4*)(ib + vb);
        int4 cv = *(const int4*)(cb + vb);
        float a0[4] = {f0.x, f0.y, f0.z, f0.w};
        float a1[4] = {f1.x, f1.y, f1.z, f1.w};
        float a2[4] = {f2.x, f2.y, f2.z, f2.w};
        int ia[4] = {iv.x, iv.y, iv.z, iv.w};
        int ca[4] = {cv.x, cv.y, cv.z, cv.w};
#pragma unroll
        for (int k = 0; k < 4; k++) {
            int v = vb + k;
            int id = ia[k];
            float s0 = fminf(fmaxf(a0[k], -15.5f), 15.5f);
            float s1 = fminf(fmaxf(a1[k], -15.5f), 15.5f);
            float s2 = fminf(fmaxf(a2[k], -15.5f), 15.5f);
            unsigned xi = v & 255;
            unsigned yi = (v >> 8) & 255;
            unsigned zi = (unsigned)v >> 16;
            unsigned long long* base = wacc[warp][id];
            unsigned q0 = __float2uint_rn((s0 + 16.0f) * 256.0f);
            unsigned q1 = __float2uint_rn((s1 + 16.0f) * 256.0f);
            unsigned q2 = __float2uint_rn((s2 + 16.0f) * 256.0f);
            unsigned r0 = __float2uint_rn(s0 * s0 * 32.0f);
            unsigned r1 = __float2uint_rn(s1 * s1 * 32.0f);
            unsigned r2 = __float2uint_rn(s2 * s2 * 32.0f);
            atomicAdd(&base[0], (unsigned long long)xi
                                | ((unsigned long long)yi << 17)
                                | ((unsigned long long)zi << 34)
                                | (1ull << 48));
            atomicAdd(&base[1], (unsigned long long)q0
                                | ((unsigned long long)q1 << 21)
                                | ((unsigned long long)q2 << 42));
            atomicAdd(&base[2], (unsigned long long)r0
                                | ((unsigned long long)r1 << 21)
                                | ((unsigned long long)r2 << 42));
            if (ca[k] != 0) {   // centers are ~1-per-volume rare: direct global
                int bi = b * NSG + id;
                atomicAdd(&g_acc[OFF_CCNT + bi], 1.0f);
                atomicAdd(&g_acc[OFF_CXYZ + bi * 3 + 0], (float)xi * (1.0f / 1023.0f));
                atomicAdd(&g_acc[OFF_CXYZ + bi * 3 + 1], (float)yi * (1.0f / 1023.0f));
                atomicAdd(&g_acc[OFF_CXYZ + bi * 3 + 2], (float)zi * (1.0f / 31.0f));
            }
        }
    }
    __syncthreads();

    // decode per-warp packs -> block-level float accumulation
    if (lane < NSG) {
        unsigned long long pA = wacc[warp][lane][0];
        unsigned long long pB = wacc[warp][lane][1];
        unsigned long long pC = wacc[warp][lane][2];
        float cnt = (float)(unsigned)(pA >> 48);
        float xs = (float)(unsigned)(pA & 0x1FFFFu) * (1.0f / 1023.0f);
        float ys = (float)(unsigned)((pA >> 17) & 0x1FFFFu) * (1.0f / 1023.0f);
        float zs = (float)(unsigned)((pA >> 34) & 0x3FFFu) * (1.0f / 31.0f);
        float s0s = (float)(unsigned)(pB & 0x1FFFFFu) * (1.0f / 256.0f) - 16.0f * cnt;
        float s1s = (float)(unsigned)((pB >> 21) & 0x1FFFFFu) * (1.0f / 256.0f) - 16.0f * cnt;
        float s2s = (float)(unsigned)((pB >> 42) & 0x1FFFFFu) * (1.0f / 256.0f) - 16.0f * cnt;
        float r0s = (float)(unsigned)(pC & 0x1FFFFFu) * (1.0f / 32.0f);
        float r1s = (float)(unsigned)((pC >> 21) & 0x1FFFFFu) * (1.0f / 32.0f);
        float r2s = (float)(unsigned)((pC >> 42) & 0x1FFFFFu) * (1.0f / 32.0f);
        float* d = sm + lane * 10;
        atomicAdd(d + 0, cnt);
        atomicAdd(d + 1, s0s);
        atomicAdd(d + 2, s1s);
        atomicAdd(d + 3, s2s);
        atomicAdd(d + 4, r0s);
        atomicAdd(d + 5, r1s);
        atomicAdd(d + 6, r2s);
        atomicAdd(d + 7, xs);
        atomicAdd(d + 8, ys);
        atomicAdd(d + 9, zs);
    }
    __syncthreads();
    if (tid < NSG * 10) {
        int id = tid / 10, f = tid % 10;
        float vsm = sm[tid];
        if (vsm != 0.0f) {
            int bi = b * NSG + id;
            float* dst;
            if (f == 0)      dst = &g_acc[OFF_CNT  + bi];
            else if (f < 4)  dst = &g_acc[OFF_SSUM + bi * 3 + (f - 1)];
            else if (f < 7)  dst = &g_acc[OFF_SSQ  + bi * 3 + (f - 4)];
            else             dst = &g_acc[OFF_XYZ  + bi * 3 + (f - 7)];
            atomicAdd(dst, vsm);
        }
    }
}

// ---------------------------------------------------------------- params (+ zero stats accumulators)
__global__ void k_params() {
    int t = threadIdx.x;
    if (t >= BB * NSG) return;
    int b = t / NSG, id = t % NSG;
    float cnt = g_acc[OFF_CNT + t];
    float safe = fmaxf(cnt, 1.0f);
    float varsum = 0.0f;
    float m[3];
    float xyz[3], cxyz[3];
#pragma unroll
    for (int c = 0; c < 3; c++) {
        float ss = g_acc[OFF_SSUM + t * 3 + c];
        float sq = g_acc[OFF_SSQ + t * 3 + c];
        float mm = ss / safe;
        m[c] = mm;
        varsum += (sq - 2.0f * mm * ss + cnt * mm * mm) / safe;
        xyz[c] = g_acc[OFF_XYZ + t * 3 + c];
        cxyz[c] = g_acc[OFF_CXYZ + t * 3 + c];
    }
    float ccnt = g_acc[OFF_CCNT + t];
    // zero for next graph replay
    g_acc[OFF_CNT + t] = 0.0f;
    g_acc[OFF_CCNT + t] = 0.0f;
#pragma unroll
    for (int c = 0; c < 3; c++) {
        g_acc[OFF_SSUM + t * 3 + c] = 0.0f;
        g_acc[OFF_SSQ + t * 3 + c] = 0.0f;
        g_acc[OFF_XYZ + t * 3 + c] = 0.0f;
        g_acc[OFF_CXYZ + t * 3 + c] = 0.0f;
    }
    if (id >= 1) {
        atomicAdd(&g_acc[OFF_VAR + b], varsum * (1.0f / (3.0f * NI)));
        bool one = (ccnt == 1.0f);
        int p = (b * NI + (id - 1)) * 3;
#pragma unroll
        for (int c = 0; c < 3; c++) {
            float cen = one ? cxyz[c] : xyz[c] / safe;
            g_acc[OFF_CEN + p + c] = cen;
            // NEGATED + pre-scaled by log2(e): k_dist computes d = ex2(sum)
            g_acc[OFF_S + p + c] = -expf(10.0f * m[c]) * 1.4426950408889634f;
        }
    }
}

// ---------------------------------------------------------------- nop (profiler alignment: puts k_dist at capture index 5)
__global__ void k_nop() {}

// ---------------------------------------------------------------- dist + SMEM histogram + seed loss
// grid (DGRID, BB, 4) = 888 blocks, single wave at 6 blocks/SM.
// Params in smem, read via VECTOR LDS (v4+v2 per instance, asm volatile so
// they stay iteration-local): 8 LDS/voxel instead of 24.
// Unified u16-packed smem hist: regions [0..3]=bg, [4..7]=fg (32KB); max
// per-(block,inst,bin) count <= 18944 < 65535, no overflow.
__global__ void __launch_bounds__(256, 6) k_dist(const float* __restrict__ pred,
                                                 const int* __restrict__ inst,
                                                 const int* __restrict__ lab) {
    __shared__ unsigned shist[8 * NBINS / 2];     // 32KB
    __shared__ float spar[32];                    // 4 inst x 8 (S0,S1,S2,C0,C1,C2,pad,pad)
    __shared__ float r1[256], r2[256];
    int b = blockIdx.y;
    int quart = blockIdx.z;          // instances [quart*4, quart*4+4)
    int nbase = quart * 4;

    if (threadIdx.x < 32) {
        int j = threadIdx.x >> 3, c = threadIdx.x & 7;
        int p = (b * NI + nbase + j) * 3;
        float val = 0.0f;
        if (c < 3)      val = g_acc[OFF_S + p + c];
        else if (c < 6) val = g_acc[OFF_CEN + p + (c - 3)];
        spar[threadIdx.x] = val;
    }
    for (int i = threadIdx.x; i < 8 * NBINS / 2; i += 256) shist[i] = 0u;
    __syncthreads();
    unsigned spar_a = smem_u32(spar);

    const float* pb = pred + (size_t)b * NCH * VV;
    const int* ib = inst + (size_t)b * VV;
    const int* lb = lab + (size_t)b * VV;

    float accbg = 0.0f, accfg = 0.0f;

    for (int v = blockIdx.x * 256 + threadIdx.x; v < VV; v += DGRID * 256) {
        float x = (float)(v & 255) * (1.0f / 1023.0f);
        float y = (float)((v >> 8) & 255) * (1.0f / 1023.0f);
        float z = (float)(v >> 16) * (1.0f / 31.0f);
        float e0 = fast_tanh(pb[v]) + x;
        float e1 = fast_tanh(pb[VV + v]) + y;
        float e2 = fast_tanh(pb[2 * VV + v]) + z;
        int id = ib[v];
        float down = 0.0f;
#pragma unroll
        for (int j = 0; j < 4; j++) {
            float S0, S1, S2, C0, C1, C2;
            lds_v4(S0, S1, S2, C0, spar_a + (j << 5));
            lds_v2(C1, C2, spar_a + (j << 5) + 16);
            float dx = e0 - C0, dy = e1 - C1, dz = e2 - C2;
            float arg = S0 * dx * dx + S1 * dy * dy + S2 * dz * dz;
            float d = fast_ex2(arg);                // S already negative*log2e
            int fg = (id == nbase + j + 1) ? 1 : 0;
            if (fg) down = d;
            // shared bin base: it = floor(d*NBINS); bg bin = it, fg bin = NBINS-1-it
            int it = (int)(d * (float)NBINS);
            it = min(it, NBINS - 1);
            int bin = fg ? (NBINS - 1 - it) : it;
            unsigned addv = 1u << ((bin & 1) << 4);
            atomicAdd(&shist[((j + (fg << 2)) << 10) | (bin >> 1)], addv);
        }
        bool own = (id > nbase && id <= nbase + 4);
        bool bg = (quart == 0) && (lb[v] == 0);
        if (own | bg) {
            float sd = 1.0f / (1.0f + __expf(-pb[6 * VV + v]));
            if (own) {
                float t = sd - down;
                accfg += t * t;
            }
            if (bg) accbg += sd * sd;
        }
    }

    __syncthreads();
    // flush: decode u16 halves, pre-aggregated REDs to global fg/bg hists
    for (int i = threadIdx.x; i < 8 * NBINS / 2; i += 256) {
        unsigned c = shist[i];
        int region = i >> 10;             // 0..7
        int j = region & 3;
        unsigned* dst = (region & 4) ? g_hfg : g_hbg;
        dst += (size_t)(b * NI + nbase + j) * NBINS;
        int w = i & 1023;                 // word -> bins 2w, 2w+1
        unsigned lo = c & 0xFFFFu, hi = c >> 16;
        if (lo) atomicAdd(&dst[2 * w], lo);
        if (hi) atomicAdd(&dst[2 * w + 1], hi);
    }

    int t = threadIdx.x;
    r1[t] = accbg;
    r2[t] = accfg;
    __syncthreads();
    for (int s = 128; s > 0; s >>= 1) {
        if (t < s) { r1[t] += r1[t + s]; r2[t] += r2[t + s]; }
        __syncthreads();
    }
    if (t == 0) {
        if (quart == 0) atomicAdd(&g_acc[OFF_SBG + b], r1[0]);
        atomicAdd(&g_acc[OFF_SFG + b], r2[0]);
    }
}

// ---------------------------------------------------------------- lovasz (+ self-wipe + folded final)
// one block per (b,n); 1024 threads; CH=2 bins/thread; shfl-based prefix scan.
// Last block (ticket) combines all losses and writes out[0].
__global__ void __launch_bounds__(1024) k_lovasz(float* out) {
    int bn = blockIdx.x;       // b*16 + n
    int b = bn >> 4;
    unsigned* HF = g_hfg + (size_t)bn * NBINS;
    unsigned* HB = g_hbg + (size_t)bn * NBINS;
    const int CH = NBINS / 1024;  // 2
    int t = threadIdx.x;
    int lane = t & 31, warp = t >> 5;

    // load my bins (descending error order: rank r = t*CH+i, bin = NBINS-1-r)
    float fA[CH], bA[CH];
    float locF = 0.0f, locB = 0.0f;
#pragma unroll
    for (int i = 0; i < CH; i++) {
        int bin = NBINS - 1 - (t * CH + i);
        fA[i] = (float)HF[bin];
        bA[i] = (float)HB[bin];
        locF += fA[i];
        locB += bA[i];
        HF[bin] = 0u;     // self-wipe for next replay
        HB[bin] = 0u;
    }

    // warp-level inclusive scan of (locF, locB) in thread order
    float incF = locF, incB = locB;
#pragma unroll
    for (int d = 1; d < 32; d <<= 1) {
        float vF = __shfl_up_sync(0xffffffffu, incF, d);
        float vB = __shfl_up_sync(0xffffffffu, incB, d);
        if (lane >= d) { incF += vF; incB += vB; }
    }
    __shared__ float wF[32], wB[32];
    __shared__ float sred[1024];
    __shared__ int sMinR;
    if (t == 0) sMinR = NBINS;
    if (lane == 31) { wF[warp] = incF; wB[warp] = incB; }
    __syncthreads();
    float offF = 0.0f, offB = 0.0f, G = 0.0f;
#pragma unroll
    for (int w = 0; w < 32; w++) {
        float f = wF[w];
        if (w < warp) { offF += f; offB += wB[w]; }
        G += f;
    }
    float P = offF + incF - locF;   // exclusive prefix (fg)
    float Q = offB + incB - locB;   // exclusive prefix (bg)

    float contrib = 0.0f;
    if (G > 0.0f) {
#pragma unroll
        for (int i = 0; i < CH; i++) {
            float f = fA[i], bb = bA[i];
            if (f > 0.0f || bb > 0.0f) {
                int bin = NBINS - 1 - (t * CH + i);
                float e = ((float)bin + 0.5f) * (2.0f / NBINS);
                float gq = G + Q;
                float num = (G - P) * bb + f * gq;   // cancellation-free jacc delta
                float den = gq * (gq + bb);
                contrib += e * num / den;
                P += f;
                Q += bb;
            }
        }
    } else {  // degenerate: no fg voxels -> loss = max error present
#pragma unroll
        for (int i = 0; i < CH; i++) {
            if (fA[i] > 0.0f || bA[i] > 0.0f) {
                atomicMin(&sMinR, t * CH + i);
                break;
            }
        }
    }
    sred[t] = contrib;
    __syncthreads();
    for (int s2 = 512; s2 > 0; s2 >>= 1) {
        if (t < s2) sred[t] += sred[t + s2];
        __syncthreads();
    }
    if (t == 0) {
        float total = sred[0];
        if (G <= 0.0f && sMinR < NBINS)
            total = ((float)(NBINS - 1 - sMinR) + 0.5f) * (2.0f / NBINS);
        atomicAdd(&g_acc[OFF_ILOSS + b], total);
        __threadfence();
        unsigned tk = atomicAdd(&g_ticket, 1u);
        if (tk == (unsigned)(BB * NI - 1)) {        // last block: fold final
            volatile float* ga = g_acc;
            float r = 0.0f;
            for (int b2 = 0; b2 < BB; b2++) {
                float il = ga[OFF_ILOSS + b2] * (1.0f / NI);
                float vl = ga[OFF_VAR + b2];
                float sl = (ga[OFF_SBG + b2] + 10.0f * ga[OFF_SFG + b2]) * (1.0f / VV);
                r += il + 10.0f * vl + sl;
                ga[OFF_ILOSS + b2] = 0.0f;
                ga[OFF_VAR + b2] = 0.0f;
                ga[OFF_SBG + b2] = 0.0f;
                ga[OFF_SFG + b2] = 0.0f;
            }
            out[0] = r * (1.0f / BB);
            g_ticket = 0u;                           // reset for next replay
        }
    }
}

// ---------------------------------------------------------------- launch
extern "C" void kernel_launch(void* const* d_in, const int* in_sizes, int n_in,
                              void* d_out, int out_size) {
    const float* pred = (const float*)d_in[0];
    const int* inst = (const int*)d_in[1];
    const int* lab = (const int*)d_in[2];
    const int* cent = (const int*)d_in[3];

    {
        dim3 g(1024, BB);
        k_stats<<<g, 256>>>(pred, inst, cent);
    }
    k_params<<<1, 64>>>();
    k_nop<<<1, 1>>>();   // aligns ncu capture (-s 5) onto k_dist
    {
        dim3 g(DGRID, BB, 4);
        k_dist<<<g, 256>>>(pred, inst, lab);
    }
    k_lovasz<<<BB * NI, 1024>>>((float*)d_out);
}

// round 15
// speedup vs baseline: 1.7398x; 1.0801x over previous
#include <cuda_runtime.h>

#define BB 2
#define NCH 7
#define VV 2097152          // 32*256*256
#define NI 16
#define NSG 17
#define NBINS 1024
#define DGRID 111           // 111*2*4 = 888 blocks = exactly 6/SM * 148 SMs

// accumulator layout (floats)
#define OFF_CNT   0          // BB*NSG
#define OFF_SSUM  34         // BB*NSG*3
#define OFF_SSQ   136
#define OFF_XYZ   238
#define OFF_CCNT  340
#define OFF_CXYZ  374
#define OFF_VAR   476        // BB
#define OFF_SBG   478
#define OFF_SFG   480
#define OFF_ILOSS 482
#define OFF_P     484        // BB*NI*8: S0,S1,S2,T0,T1,T2,K,pad (quadratic form)
#define ACC_N     740

__device__ float g_acc[ACC_N];                  // zero-init; self-cleaning
__device__ unsigned g_hfg[BB * NI * NBINS];     // fg counts, indexed by it
__device__ unsigned g_hbg[BB * NI * NBINS];     // bg counts, indexed by it
__device__ unsigned g_ticket;                   // lovasz completion ticket

__device__ __forceinline__ float fast_tanh(float x) {
    float r;
    asm("tanh.approx.f32 %0, %1;" : "=f"(r) : "f"(x));
    return r;
}
__device__ __forceinline__ float fast_ex2(float x) {
    float r;
    asm("ex2.approx.f32 %0, %1;" : "=f"(r) : "f"(x));
    return r;
}
__device__ __forceinline__ unsigned smem_u32(const void* p) {
    unsigned a;
    asm("{ .reg .u64 t; cvta.to.shared.u64 t, %1; cvt.u32.u64 %0, t; }"
        : "=r"(a) : "l"(p));
    return a;
}
__device__ __forceinline__ void lds_v4(float& a, float& b, float& c, float& d,
                                       unsigned addr) {
    asm volatile("ld.shared.v4.f32 {%0,%1,%2,%3}, [%4];"
                 : "=f"(a), "=f"(b), "=f"(c), "=f"(d) : "r"(addr));
}

// ---------------------------------------------------------------- stats
// Per-warp fixed-point packed accumulators (3 u64 per id), exact/bounded for
// exactly 256 voxels per warp. grid (1024, BB), 256 thr, 8 voxels/thread.
__global__ void __launch_bounds__(256) k_stats(const float* __restrict__ pred,
                                               const int* __restrict__ inst,
                                               const int* __restrict__ cent) {
    int b = blockIdx.y;
    __shared__ unsigned long long wacc[8][NSG][3];
    __shared__ float sm[NSG * 10];
    int tid = threadIdx.x;
    int warp = tid >> 5, lane = tid & 31;

    for (int j = tid; j < 8 * NSG * 3; j += 256)
        ((unsigned long long*)wacc)[j] = 0ull;
    for (int j = tid; j < NSG * 10; j += 256) sm[j] = 0.0f;
    __syncthreads();

    const float* sig = pred + ((size_t)b * NCH + 3) * VV;
    const int* ib = inst + (size_t)b * VV;
    const int* cb = cent + (size_t)b * VV;

    int v0 = (blockIdx.x * 256 + tid) * 8;
#pragma unroll
    for (int g = 0; g < 2; g++) {
        int vb = v0 + g * 4;
        float4 f0 = *(const float4*)(sig + vb);
        float4 f1 = *(const float4*)(sig + VV + vb);
        float4 f2 = *(const float4*)(sig + 2 * VV + vb);
        int4 iv = *(const int4*)(ib + vb);
        int4 cv = *(const int4*)(cb + vb);
        float a0[4] = {f0.x, f0.y, f0.z, f0.w};
        float a1[4] = {f1.x, f1.y, f1.z, f1.w};
        float a2[4] = {f2.x, f2.y, f2.z, f2.w};
        int ia[4] = {iv.x, iv.y, iv.z, iv.w};
        int ca[4] = {cv.x, cv.y, cv.z, cv.w};
#pragma unroll
        for (int k = 0; k < 4; k++) {
            int v = vb + k;
            int id = ia[k];
            float s0 = fminf(fmaxf(a0[k], -15.5f), 15.5f);
            float s1 = fminf(fmaxf(a1[k], -15.5f), 15.5f);
            float s2 = fminf(fmaxf(a2[k], -15.5f), 15.5f);
            unsigned xi = v & 255;
            unsigned yi = (v >> 8) & 255;
            unsigned zi = (unsigned)v >> 16;
            unsigned long long* base = wacc[warp][id];
            unsigned q0 = __float2uint_rn((s0 + 16.0f) * 256.0f);
            unsigned q1 = __float2uint_rn((s1 + 16.0f) * 256.0f);
            unsigned q2 = __float2uint_rn((s2 + 16.0f) * 256.0f);
            unsigned r0 = __float2uint_rn(s0 * s0 * 32.0f);
            unsigned r1 = __float2uint_rn(s1 * s1 * 32.0f);
            unsigned r2 = __float2uint_rn(s2 * s2 * 32.0f);
            atomicAdd(&base[0], (unsigned long long)xi
                                | ((unsigned long long)yi << 17)
                                | ((unsigned long long)zi << 34)
                                | (1ull << 48));
            atomicAdd(&base[1], (unsigned long long)q0
                                | ((unsigned long long)q1 << 21)
                                | ((unsigned long long)q2 << 42));
            atomicAdd(&base[2], (unsigned long long)r0
                                | ((unsigned long long)r1 << 21)
                                | ((unsigned long long)r2 << 42));
            if (ca[k] != 0) {   // centers are ~1-per-volume rare: direct global
                int bi = b * NSG + id;
                atomicAdd(&g_acc[OFF_CCNT + bi], 1.0f);
                atomicAdd(&g_acc[OFF_CXYZ + bi * 3 + 0], (float)xi * (1.0f / 1023.0f));
                atomicAdd(&g_acc[OFF_CXYZ + bi * 3 + 1], (float)yi * (1.0f / 1023.0f));
                atomicAdd(&g_acc[OFF_CXYZ + bi * 3 + 2], (float)zi * (1.0f / 31.0f));
            }
        }
    }
    __syncthreads();

    // decode per-warp packs -> block-level float accumulation
    if (lane < NSG) {
        unsigned long long pA = wacc[warp][lane][0];
        unsigned long long pB = wacc[warp][lane][1];
        unsigned long long pC = wacc[warp][lane][2];
        float cnt = (float)(unsigned)(pA >> 48);
        float xs = (float)(unsigned)(pA & 0x1FFFFu) * (1.0f / 1023.0f);
        float ys = (float)(unsigned)((pA >> 17) & 0x1FFFFu) * (1.0f / 1023.0f);
        float zs = (float)(unsigned)((pA >> 34) & 0x3FFFu) * (1.0f / 31.0f);
        float s0s = (float)(unsigned)(pB & 0x1FFFFFu) * (1.0f / 256.0f) - 16.0f * cnt;
        float s1s = (float)(unsigned)((pB >> 21) & 0x1FFFFFu) * (1.0f / 256.0f) - 16.0f * cnt;
        float s2s = (float)(unsigned)((pB >> 42) & 0x1FFFFFu) * (1.0f / 256.0f) - 16.0f * cnt;
        float r0s = (float)(unsigned)(pC & 0x1FFFFFu) * (1.0f / 32.0f);
        float r1s = (float)(unsigned)((pC >> 21) & 0x1FFFFFu) * (1.0f / 32.0f);
        float r2s = (float)(unsigned)((pC >> 42) & 0x1FFFFFu) * (1.0f / 32.0f);
        float* d = sm + lane * 10;
        atomicAdd(d + 0, cnt);
        atomicAdd(d + 1, s0s);
        atomicAdd(d + 2, s1s);
        atomicAdd(d + 3, s2s);
        atomicAdd(d + 4, r0s);
        atomicAdd(d + 5, r1s);
        atomicAdd(d + 6, r2s);
        atomicAdd(d + 7, xs);
        atomicAdd(d + 8, ys);
        atomicAdd(d + 9, zs);
    }
    __syncthreads();
    if (tid < NSG * 10) {
        int id = tid / 10, f = tid % 10;
        float vsm = sm[tid];
        if (vsm != 0.0f) {
            int bi = b * NSG + id;
            float* dst;
            if (f == 0)      dst = &g_acc[OFF_CNT  + bi];
            else if (f < 4)  dst = &g_acc[OFF_SSUM + bi * 3 + (f - 1)];
            else if (f < 7)  dst = &g_acc[OFF_SSQ  + bi * 3 + (f - 4)];
            else             dst = &g_acc[OFF_XYZ  + bi * 3 + (f - 7)];
            atomicAdd(dst, vsm);
        }
    }
}

// ---------------------------------------------------------------- params (+ zero stats accumulators)
// Produces quadratic-form params per instance: arg = K + sum_c(S_c e_c^2 + T_c e_c)
// where S_c = -exp(10 m_c) * log2e, T_c = -2 S_c C_c, K = sum S_c C_c^2.
__global__ void k_params() {
    int t = threadIdx.x;
    if (t >= BB * NSG) return;
    int b = t / NSG, id = t % NSG;
    float cnt = g_acc[OFF_CNT + t];
    float safe = fmaxf(cnt, 1.0f);
    float varsum = 0.0f;
    float m[3];
    float xyz[3], cxyz[3];
#pragma unroll
    for (int c = 0; c < 3; c++) {
        float ss = g_acc[OFF_SSUM + t * 3 + c];
        float sq = g_acc[OFF_SSQ + t * 3 + c];
        float mm = ss / safe;
        m[c] = mm;
        varsum += (sq - 2.0f * mm * ss + cnt * mm * mm) / safe;
        xyz[c] = g_acc[OFF_XYZ + t * 3 + c];
        cxyz[c] = g_acc[OFF_CXYZ + t * 3 + c];
    }
    float ccnt = g_acc[OFF_CCNT + t];
    // zero for next graph replay
    g_acc[OFF_CNT + t] = 0.0f;
    g_acc[OFF_CCNT + t] = 0.0f;
#pragma unroll
    for (int c = 0; c < 3; c++) {
        g_acc[OFF_SSUM + t * 3 + c] = 0.0f;
        g_acc[OFF_SSQ + t * 3 + c] = 0.0f;
        g_acc[OFF_XYZ + t * 3 + c] = 0.0f;
        g_acc[OFF_CXYZ + t * 3 + c] = 0.0f;
    }
    if (id >= 1) {
        atomicAdd(&g_acc[OFF_VAR + b], varsum * (1.0f / (3.0f * NI)));
        bool one = (ccnt == 1.0f);
        int p = (b * NI + (id - 1)) * 8;
        float K = 0.0f;
#pragma unroll
        for (int c = 0; c < 3; c++) {
            float cen = one ? cxyz[c] : xyz[c] / safe;
            float S = -expf(10.0f * m[c]) * 1.4426950408889634f;
            g_acc[OFF_P + p + c] = S;
            g_acc[OFF_P + p + 3 + c] = -2.0f * S * cen;
            K += S * cen * cen;
        }
        g_acc[OFF_P + p + 6] = K;
        g_acc[OFF_P + p + 7] = 0.0f;
    }
}

// ---------------------------------------------------------------- nop (profiler alignment: puts k_dist at capture index 5)
__global__ void k_nop() {}

// ---------------------------------------------------------------- dist + SMEM histogram + seed loss
// grid (DGRID, BB, 4) = 888 blocks, single wave at 6 blocks/SM.
// Quadratic-form distance (6 FMA/pair, voxel squares amortized); u32 smem
// hist, 8 regions of 1024 bins (32KB): region = (j<<1)|fg, both indexed by
// it = floor(d*1024). fg reversal handled in k_lovasz.
__global__ void __launch_bounds__(256, 6) k_dist(const float* __restrict__ pred,
                                                 const int* __restrict__ inst,
                                                 const int* __restrict__ lab) {
    __shared__ unsigned shist[8 * NBINS];         // 32KB u32
    __shared__ float spar[32];                    // 4 inst x 8 (S0,S1,S2,T0,T1,T2,K,pad)
    __shared__ float r1[256], r2[256];
    int b = blockIdx.y;
    int quart = blockIdx.z;          // instances [quart*4, quart*4+4)
    int nbase = quart * 4;

    if (threadIdx.x < 32) {
        int j = threadIdx.x >> 3, c = threadIdx.x & 7;
        int p = (b * NI + nbase + j) * 8;
        spar[threadIdx.x] = g_acc[OFF_P + p + c];
    }
    for (int i = threadIdx.x; i < 8 * NBINS; i += 256) shist[i] = 0u;
    __syncthreads();
    unsigned spar_a = smem_u32(spar);

    const float* pb = pred + (size_t)b * NCH * VV;
    const int* ib = inst + (size_t)b * VV;
    const int* lb = lab + (size_t)b * VV;

    float accbg = 0.0f, accfg = 0.0f;

    for (int v = blockIdx.x * 256 + threadIdx.x; v < VV; v += DGRID * 256) {
        float x = (float)(v & 255) * (1.0f / 1023.0f);
        float y = (float)((v >> 8) & 255) * (1.0f / 1023.0f);
        float z = (float)(v >> 16) * (1.0f / 31.0f);
        float e0 = fast_tanh(pb[v]) + x;
        float e1 = fast_tanh(pb[VV + v]) + y;
        float e2 = fast_tanh(pb[2 * VV + v]) + z;
        float q0 = e0 * e0, q1 = e1 * e1, q2 = e2 * e2;   // amortized squares
        int id = ib[v];
        float down = 0.0f;
#pragma unroll
        for (int j = 0; j < 4; j++) {
            float S0, S1, S2, T0, T1, T2, K, PD;
            lds_v4(S0, S1, S2, T0, spar_a + (j << 5));
            lds_v4(T1, T2, K, PD, spar_a + (j << 5) + 16);
            float arg = K;
            arg = fmaf(S0, q0, arg);
            arg = fmaf(T0, e0, arg);
            arg = fmaf(S1, q1, arg);
            arg = fmaf(T1, e1, arg);
            arg = fmaf(S2, q2, arg);
            arg = fmaf(T2, e2, arg);
            float d = fast_ex2(arg);                // S pre-negated*log2e
            int fg = (id == nbase + j + 1) ? 1 : 0;
            if (fg) down = d;
            int it = (int)(d * (float)NBINS);
            it = min(it, NBINS - 1);
            atomicAdd(&shist[((((j << 1) | fg)) << 10) | it], 1u);
        }
        bool own = (id > nbase && id <= nbase + 4);
        bool bg = (quart == 0) && (lb[v] == 0);
        if (own | bg) {
            float sd = 1.0f / (1.0f + __expf(-pb[6 * VV + v]));
            if (own) {
                float t = sd - down;
                accfg += t * t;
            }
            if (bg) accbg += sd * sd;
        }
    }

    __syncthreads();
    // flush: pre-aggregated REDs to global fg/bg hists (both it-indexed)
    for (int i = threadIdx.x; i < 8 * NBINS; i += 256) {
        unsigned c = shist[i];
        if (c) {
            int region = i >> 10;             // 0..7 = (j<<1)|fg
            int j = region >> 1;
            unsigned* dst = (region & 1) ? g_hfg : g_hbg;
            atomicAdd(&dst[(size_t)(b * NI + nbase + j) * NBINS + (i & 1023)], c);
        }
    }

    int t = threadIdx.x;
    r1[t] = accbg;
    r2[t] = accfg;
    __syncthreads();
    for (int s = 128; s > 0; s >>= 1) {
        if (t < s) { r1[t] += r1[t + s]; r2[t] += r2[t + s]; }
        __syncthreads();
    }
    if (t == 0) {
        if (quart == 0) atomicAdd(&g_acc[OFF_SBG + b], r1[0]);
        atomicAdd(&g_acc[OFF_SFG + b], r2[0]);
    }
}

// ---------------------------------------------------------------- lovasz (+ self-wipe + folded final)
// one block per (b,n); 1024 threads; 1 bin/thread (descending-error rank r =
// threadIdx.x). bg: bin = 1023-r (e=2d ascending in it); fg: it = r (e=2-2d).
// Last block (ticket) combines all losses and writes out[0].
__global__ void __launch_bounds__(1024) k_lovasz(float* out) {
    int bn = blockIdx.x;       // b*16 + n
    int b = bn >> 4;
    unsigned* HF = g_hfg + (size_t)bn * NBINS;
    unsigned* HB = g_hbg + (size_t)bn * NBINS;
    int t = threadIdx.x;
    int lane = t & 31, warp = t >> 5;

    float fA = (float)HF[t];                 // fg: it = rank
    float bA = (float)HB[NBINS - 1 - t];     // bg: bin = 1023 - rank
    HF[t] = 0u;                              // self-wipe for next replay
    HB[NBINS - 1 - t] = 0u;

    // warp-level inclusive scan in rank order
    float incF = fA, incB = bA;
#pragma unroll
    for (int d = 1; d < 32; d <<= 1) {
        float vF = __shfl_up_sync(0xffffffffu, incF, d);
        float vB = __shfl_up_sync(0xffffffffu, incB, d);
        if (lane >= d) { incF += vF; incB += vB; }
    }
    __shared__ float wF[32], wB[32];
    __shared__ float sred[1024];
    __shared__ int sMinR;
    if (t == 0) sMinR = NBINS;
    if (lane == 31) { wF[warp] = incF; wB[warp] = incB; }
    __syncthreads();
    float offF = 0.0f, offB = 0.0f, G = 0.0f;
#pragma unroll
    for (int w = 0; w < 32; w++) {
        float f = wF[w];
        if (w < warp) { offF += f; offB += wB[w]; }
        G += f;
    }
    float P = offF + incF - fA;   // exclusive prefix (fg)
    float Q = offB + incB - bA;   // exclusive prefix (bg)

    float contrib = 0.0f;
    if (G > 0.0f) {
        if (fA > 0.0f || bA > 0.0f) {
            float e = ((float)(NBINS - 1 - t) + 0.5f) * (2.0f / NBINS);
            float gq = G + Q;
            float num = (G - P) * bA + fA * gq;   // cancellation-free jacc delta
            float den = gq * (gq + bA);
            contrib = e * num / den;
        }
    } else {  // degenerate: no fg voxels -> loss = max error present
        if (fA > 0.0f || bA > 0.0f) atomicMin(&sMinR, t);
    }
    sred[t] = contrib;
    __syncthreads();
    for (int s2 = 512; s2 > 0; s2 >>= 1) {
        if (t < s2) sred[t] += sred[t + s2];
        __syncthreads();
    }
    if (t == 0) {
        float total = sred[0];
        if (G <= 0.0f && sMinR < NBINS)
            total = ((float)(NBINS - 1 - sMinR) + 0.5f) * (2.0f / NBINS);
        atomicAdd(&g_acc[OFF_ILOSS + b], total);
        __threadfence();
        unsigned tk = atomicAdd(&g_ticket, 1u);
        if (tk == (unsigned)(BB * NI - 1)) {        // last block: fold final
            volatile float* ga = g_acc;
            float r = 0.0f;
            for (int b2 = 0; b2 < BB; b2++) {
                float il = ga[OFF_ILOSS + b2] * (1.0f / NI);
                float vl = ga[OFF_VAR + b2];
                float sl = (ga[OFF_SBG + b2] + 10.0f * ga[OFF_SFG + b2]) * (1.0f / VV);
                r += il + 10.0f * vl + sl;
                ga[OFF_ILOSS + b2] = 0.0f;
                ga[OFF_VAR + b2] = 0.0f;
                ga[OFF_SBG + b2] = 0.0f;
                ga[OFF_SFG + b2] = 0.0f;
            }
            out[0] = r * (1.0f / BB);
            g_ticket = 0u;                           // reset for next replay
        }
    }
}

// ---------------------------------------------------------------- launch
extern "C" void kernel_launch(void* const* d_in, const int* in_sizes, int n_in,
                              void* d_out, int out_size) {
    const float* pred = (const float*)d_in[0];
    const int* inst = (const int*)d_in[1];
    const int* lab = (const int*)d_in[2];
    const int* cent = (const int*)d_in[3];

    {
        dim3 g(1024, BB);
        k_stats<<<g, 256>>>(pred, inst, cent);
    }
    k_params<<<1, 64>>>();
    k_nop<<<1, 1>>>();   // aligns ncu capture (-s 5) onto k_dist
    {
        dim3 g(DGRID, BB, 4);
        k_dist<<<g, 256>>>(pred, inst, lab);
    }
    k_lovasz<<<BB * NI, 1024>>>((float*)d_out);
}

// round 16
// speedup vs baseline: 1.8777x; 1.0792x over previous
#include <cuda_runtime.h>

#define BB 2
#define NCH 7
#define VV 2097152          // 32*256*256
#define NI 16
#define NSG 17
#define NBINS 1024
#define DGRID 222           // 222*2*2 = 888 blocks = exactly 6/SM * 148 SMs

// accumulator layout (floats)
#define OFF_CNT   0          // BB*NSG
#define OFF_SSUM  34         // BB*NSG*3
#define OFF_SSQ   136
#define OFF_XYZ   238
#define OFF_CCNT  340
#define OFF_CXYZ  374
#define OFF_VAR   476        // BB
#define OFF_SBG   478
#define OFF_SFG   480
#define OFF_ILOSS 482
#define OFF_P     484        // BB*NI*8: S0,S1,S2,T0,T1,T2,K,pad (quadratic form)
#define ACC_N     740

__device__ float g_acc[ACC_N];                  // zero-init; self-cleaning
__device__ unsigned g_hfg[BB * NI * NBINS];     // fg counts, indexed by it
__device__ unsigned g_hbg[BB * NI * NBINS];     // bg counts, indexed by it
__device__ unsigned g_ticket;                   // lovasz completion ticket

__device__ __forceinline__ float fast_tanh(float x) {
    float r;
    asm("tanh.approx.f32 %0, %1;" : "=f"(r) : "f"(x));
    return r;
}
__device__ __forceinline__ float fast_ex2(float x) {
    float r;
    asm("ex2.approx.f32 %0, %1;" : "=f"(r) : "f"(x));
    return r;
}
__device__ __forceinline__ unsigned smem_u32(const void* p) {
    unsigned a;
    asm("{ .reg .u64 t; cvta.to.shared.u64 t, %1; cvt.u32.u64 %0, t; }"
        : "=r"(a) : "l"(p));
    return a;
}
__device__ __forceinline__ void lds_v4(float& a, float& b, float& c, float& d,
                                       unsigned addr) {
    asm volatile("ld.shared.v4.f32 {%0,%1,%2,%3}, [%4];"
                 : "=f"(a), "=f"(b), "=f"(c), "=f"(d) : "r"(addr));
}

// ---------------------------------------------------------------- stats
// Per-warp fixed-point packed accumulators (3 u64 per id), exact/bounded for
// exactly 256 voxels per warp. grid (1024, BB), 256 thr, 8 voxels/thread.
__global__ void __launch_bounds__(256) k_stats(const float* __restrict__ pred,
                                               const int* __restrict__ inst,
                                               const int* __restrict__ cent) {
    int b = blockIdx.y;
    __shared__ unsigned long long wacc[8][NSG][3];
    __shared__ float sm[NSG * 10];
    int tid = threadIdx.x;
    int warp = tid >> 5, lane = tid & 31;

    for (int j = tid; j < 8 * NSG * 3; j += 256)
        ((unsigned long long*)wacc)[j] = 0ull;
    for (int j = tid; j < NSG * 10; j += 256) sm[j] = 0.0f;
    __syncthreads();

    const float* sig = pred + ((size_t)b * NCH + 3) * VV;
    const int* ib = inst + (size_t)b * VV;
    const int* cb = cent + (size_t)b * VV;

    int v0 = (blockIdx.x * 256 + tid) * 8;
#pragma unroll
    for (int g = 0; g < 2; g++) {
        int vb = v0 + g * 4;
        float4 f0 = *(const float4*)(sig + vb);
        float4 f1 = *(const float4*)(sig + VV + vb);
        float4 f2 = *(const float4*)(sig + 2 * VV + vb);
        int4 iv = *(const int4*)(ib + vb);
        int4 cv = *(const int4*)(cb + vb);
        float a0[4] = {f0.x, f0.y, f0.z, f0.w};
        float a1[4] = {f1.x, f1.y, f1.z, f1.w};
        float a2[4] = {f2.x, f2.y, f2.z, f2.w};
        int ia[4] = {iv.x, iv.y, iv.z, iv.w};
        int ca[4] = {cv.x, cv.y, cv.z, cv.w};
#pragma unroll
        for (int k = 0; k < 4; k++) {
            int v = vb + k;
            int id = ia[k];
            float s0 = fminf(fmaxf(a0[k], -15.5f), 15.5f);
            float s1 = fminf(fmaxf(a1[k], -15.5f), 15.5f);
            float s2 = fminf(fmaxf(a2[k], -15.5f), 15.5f);
            unsigned xi = v & 255;
            unsigned yi = (v >> 8) & 255;
            unsigned zi = (unsigned)v >> 16;
            unsigned long long* base = wacc[warp][id];
            unsigned q0 = __float2uint_rn((s0 + 16.0f) * 256.0f);
            unsigned q1 = __float2uint_rn((s1 + 16.0f) * 256.0f);
            unsigned q2 = __float2uint_rn((s2 + 16.0f) * 256.0f);
            unsigned r0 = __float2uint_rn(s0 * s0 * 32.0f);
            unsigned r1 = __float2uint_rn(s1 * s1 * 32.0f);
            unsigned r2 = __float2uint_rn(s2 * s2 * 32.0f);
            atomicAdd(&base[0], (unsigned long long)xi
                                | ((unsigned long long)yi << 17)
                                | ((unsigned long long)zi << 34)
                                | (1ull << 48));
            atomicAdd(&base[1], (unsigned long long)q0
                                | ((unsigned long long)q1 << 21)
                                | ((unsigned long long)q2 << 42));
            atomicAdd(&base[2], (unsigned long long)r0
                                | ((unsigned long long)r1 << 21)
                                | ((unsigned long long)r2 << 42));
            if (ca[k] != 0) {   // centers are ~1-per-volume rare: direct global
                int bi = b * NSG + id;
                atomicAdd(&g_acc[OFF_CCNT + bi], 1.0f);
                atomicAdd(&g_acc[OFF_CXYZ + bi * 3 + 0], (float)xi * (1.0f / 1023.0f));
                atomicAdd(&g_acc[OFF_CXYZ + bi * 3 + 1], (float)yi * (1.0f / 1023.0f));
                atomicAdd(&g_acc[OFF_CXYZ + bi * 3 + 2], (float)zi * (1.0f / 31.0f));
            }
        }
    }
    __syncthreads();

    // decode per-warp packs -> block-level float accumulation
    if (lane < NSG) {
        unsigned long long pA = wacc[warp][lane][0];
        unsigned long long pB = wacc[warp][lane][1];
        unsigned long long pC = wacc[warp][lane][2];
        float cnt = (float)(unsigned)(pA >> 48);
        float xs = (float)(unsigned)(pA & 0x1FFFFu) * (1.0f / 1023.0f);
        float ys = (float)(unsigned)((pA >> 17) & 0x1FFFFu) * (1.0f / 1023.0f);
        float zs = (float)(unsigned)((pA >> 34) & 0x3FFFu) * (1.0f / 31.0f);
        float s0s = (float)(unsigned)(pB & 0x1FFFFFu) * (1.0f / 256.0f) - 16.0f * cnt;
        float s1s = (float)(unsigned)((pB >> 21) & 0x1FFFFFu) * (1.0f / 256.0f) - 16.0f * cnt;
        float s2s = (float)(unsigned)((pB >> 42) & 0x1FFFFFu) * (1.0f / 256.0f) - 16.0f * cnt;
        float r0s = (float)(unsigned)(pC & 0x1FFFFFu) * (1.0f / 32.0f);
        float r1s = (float)(unsigned)((pC >> 21) & 0x1FFFFFu) * (1.0f / 32.0f);
        float r2s = (float)(unsigned)((pC >> 42) & 0x1FFFFFu) * (1.0f / 32.0f);
        float* d = sm + lane * 10;
        atomicAdd(d + 0, cnt);
        atomicAdd(d + 1, s0s);
        atomicAdd(d + 2, s1s);
        atomicAdd(d + 3, s2s);
        atomicAdd(d + 4, r0s);
        atomicAdd(d + 5, r1s);
        atomicAdd(d + 6, r2s);
        atomicAdd(d + 7, xs);
        atomicAdd(d + 8, ys);
        atomicAdd(d + 9, zs);
    }
    __syncthreads();
    if (tid < NSG * 10) {
        int id = tid / 10, f = tid % 10;
        float vsm = sm[tid];
        if (vsm != 0.0f) {
            int bi = b * NSG + id;
            float* dst;
            if (f == 0)      dst = &g_acc[OFF_CNT  + bi];
            else if (f < 4)  dst = &g_acc[OFF_SSUM + bi * 3 + (f - 1)];
            else if (f < 7)  dst = &g_acc[OFF_SSQ  + bi * 3 + (f - 4)];
            else             dst = &g_acc[OFF_XYZ  + bi * 3 + (f - 7)];
            atomicAdd(dst, vsm);
        }
    }
}

// ---------------------------------------------------------------- params (+ zero stats accumulators)
// Produces quadratic-form params per instance: arg = K + sum_c(S_c e_c^2 + T_c e_c)
// where S_c = -exp(10 m_c) * log2e, T_c = -2 S_c C_c, K = sum S_c C_c^2.
__global__ void k_params() {
    int t = threadIdx.x;
    if (t >= BB * NSG) return;
    int b = t / NSG, id = t % NSG;
    float cnt = g_acc[OFF_CNT + t];
    float safe = fmaxf(cnt, 1.0f);
    float varsum = 0.0f;
    float m[3];
    float xyz[3], cxyz[3];
#pragma unroll
    for (int c = 0; c < 3; c++) {
        float ss = g_acc[OFF_SSUM + t * 3 + c];
        float sq = g_acc[OFF_SSQ + t * 3 + c];
        float mm = ss / safe;
        m[c] = mm;
        varsum += (sq - 2.0f * mm * ss + cnt * mm * mm) / safe;
        xyz[c] = g_acc[OFF_XYZ + t * 3 + c];
        cxyz[c] = g_acc[OFF_CXYZ + t * 3 + c];
    }
    float ccnt = g_acc[OFF_CCNT + t];
    // zero for next graph replay
    g_acc[OFF_CNT + t] = 0.0f;
    g_acc[OFF_CCNT + t] = 0.0f;
#pragma unroll
    for (int c = 0; c < 3; c++) {
        g_acc[OFF_SSUM + t * 3 + c] = 0.0f;
        g_acc[OFF_SSQ + t * 3 + c] = 0.0f;
        g_acc[OFF_XYZ + t * 3 + c] = 0.0f;
        g_acc[OFF_CXYZ + t * 3 + c] = 0.0f;
    }
    if (id >= 1) {
        atomicAdd(&g_acc[OFF_VAR + b], varsum * (1.0f / (3.0f * NI)));
        bool one = (ccnt == 1.0f);
        int p = (b * NI + (id - 1)) * 8;
        float K = 0.0f;
#pragma unroll
        for (int c = 0; c < 3; c++) {
            float cen = one ? cxyz[c] : xyz[c] / safe;
            float S = -expf(10.0f * m[c]) * 1.4426950408889634f;
            g_acc[OFF_P + p + c] = S;
            g_acc[OFF_P + p + 3 + c] = -2.0f * S * cen;
            K += S * cen * cen;
        }
        g_acc[OFF_P + p + 6] = K;
        g_acc[OFF_P + p + 7] = 0.0f;
    }
}

// ---------------------------------------------------------------- nop (profiler alignment: puts k_dist at capture index 5)
__global__ void k_nop() {}

// ---------------------------------------------------------------- dist + SMEM histogram + seed loss
// grid (DGRID, BB, 2) = 888 blocks, single wave at 6 blocks/SM. 8 instances
// per block (params in smem -> zero per-instance registers); each voxel is
// loaded/tanh'd only TWICE total (was 4x). bg -> u32 smem hist (8 regions x
// 1024 bins, 32KB); fg (sparse, ~4M total) -> direct global RED.
__global__ void __launch_bounds__(256, 6) k_dist(const float* __restrict__ pred,
                                                 const int* __restrict__ inst,
                                                 const int* __restrict__ lab) {
    __shared__ unsigned shist[8 * NBINS];         // 32KB u32, bg only
    __shared__ float spar[64];                    // 8 inst x 8 (S0,S1,S2,T0,T1,T2,K,pad)
    __shared__ float r1[256], r2[256];
    int b = blockIdx.y;
    int half = blockIdx.z;           // instances [half*8, half*8+8)
    int nbase = half * 8;

    if (threadIdx.x < 64) {
        int j = threadIdx.x >> 3, c = threadIdx.x & 7;
        int p = (b * NI + nbase + j) * 8;
        spar[threadIdx.x] = g_acc[OFF_P + p + c];
    }
    for (int i = threadIdx.x; i < 8 * NBINS; i += 256) shist[i] = 0u;
    __syncthreads();
    unsigned spar_a = smem_u32(spar);

    const float* pb = pred + (size_t)b * NCH * VV;
    const int* ib = inst + (size_t)b * VV;
    const int* lb = lab + (size_t)b * VV;
    unsigned* hfg = g_hfg + (size_t)(b * NI + nbase) * NBINS;

    float accbg = 0.0f, accfg = 0.0f;

    for (int v = blockIdx.x * 256 + threadIdx.x; v < VV; v += DGRID * 256) {
        float x = (float)(v & 255) * (1.0f / 1023.0f);
        float y = (float)((v >> 8) & 255) * (1.0f / 1023.0f);
        float z = (float)(v >> 16) * (1.0f / 31.0f);
        float e0 = fast_tanh(pb[v]) + x;
        float e1 = fast_tanh(pb[VV + v]) + y;
        float e2 = fast_tanh(pb[2 * VV + v]) + z;
        float q0 = e0 * e0, q1 = e1 * e1, q2 = e2 * e2;   // amortized squares
        int id = ib[v];
        float down = 0.0f;
#pragma unroll
        for (int j = 0; j < 8; j++) {
            float S0, S1, S2, T0, T1, T2, K, PD;
            lds_v4(S0, S1, S2, T0, spar_a + (j << 5));
            lds_v4(T1, T2, K, PD, spar_a + (j << 5) + 16);
            float arg = K;
            arg = fmaf(S0, q0, arg);
            arg = fmaf(T0, e0, arg);
            arg = fmaf(S1, q1, arg);
            arg = fmaf(T1, e1, arg);
            arg = fmaf(S2, q2, arg);
            arg = fmaf(T2, e2, arg);
            float d = fast_ex2(arg);                // S pre-negated*log2e
            int it = (int)(d * (float)NBINS);
            it = min(it, NBINS - 1);
            if (id == nbase + j + 1) {              // fg: sparse -> global RED
                down = d;
                atomicAdd(&hfg[(j << 10) | it], 1u);
            } else {                                // bg: dense -> smem
                atomicAdd(&shist[(j << 10) | it], 1u);
            }
        }
        bool own = (id > nbase && id <= nbase + 8);
        bool bg = (half == 0) && (lb[v] == 0);
        if (own | bg) {
            float sd = 1.0f / (1.0f + __expf(-pb[6 * VV + v]));
            if (own) {
                float t = sd - down;
                accfg += t * t;
            }
            if (bg) accbg += sd * sd;
        }
    }

    __syncthreads();
    // flush bg: pre-aggregated REDs to global hist (it-indexed)
    unsigned* hbg = g_hbg + (size_t)(b * NI + nbase) * NBINS;
    for (int i = threadIdx.x; i < 8 * NBINS; i += 256) {
        unsigned c = shist[i];
        if (c) atomicAdd(&hbg[i], c);
    }

    int t = threadIdx.x;
    r1[t] = accbg;
    r2[t] = accfg;
    __syncthreads();
    for (int s = 128; s > 0; s >>= 1) {
        if (t < s) { r1[t] += r1[t + s]; r2[t] += r2[t + s]; }
        __syncthreads();
    }
    if (t == 0) {
        if (half == 0) atomicAdd(&g_acc[OFF_SBG + b], r1[0]);
        atomicAdd(&g_acc[OFF_SFG + b], r2[0]);
    }
}

// ---------------------------------------------------------------- lovasz (+ self-wipe + folded final)
// one block per (b,n); 1024 threads; 1 bin/thread (descending-error rank r =
// threadIdx.x). bg: bin = 1023-r (e=2d ascending in it); fg: it = r (e=2-2d).
// Last block (ticket) combines all losses and writes out[0].
__global__ void __launch_bounds__(1024) k_lovasz(float* out) {
    int bn = blockIdx.x;       // b*16 + n
    int b = bn >> 4;
    unsigned* HF = g_hfg + (size_t)bn * NBINS;
    unsigned* HB = g_hbg + (size_t)bn * NBINS;
    int t = threadIdx.x;
    int lane = t & 31, warp = t >> 5;

    float fA = (float)HF[t];                 // fg: it = rank
    float bA = (float)HB[NBINS - 1 - t];     // bg: bin = 1023 - rank
    HF[t] = 0u;                              // self-wipe for next replay
    HB[NBINS - 1 - t] = 0u;

    // warp-level inclusive scan in rank order
    float incF = fA, incB = bA;
#pragma unroll
    for (int d = 1; d < 32; d <<= 1) {
        float vF = __shfl_up_sync(0xffffffffu, incF, d);
        float vB = __shfl_up_sync(0xffffffffu, incB, d);
        if (lane >= d) { incF += vF; incB += vB; }
    }
    __shared__ float wF[32], wB[32];
    __shared__ float sred[1024];
    __shared__ int sMinR;
    if (t == 0) sMinR = NBINS;
    if (lane == 31) { wF[warp] = incF; wB[warp] = incB; }
    __syncthreads();
    float offF = 0.0f, offB = 0.0f, G = 0.0f;
#pragma unroll
    for (int w = 0; w < 32; w++) {
        float f = wF[w];
        if (w < warp) { offF += f; offB += wB[w]; }
        G += f;
    }
    float P = offF + incF - fA;   // exclusive prefix (fg)
    float Q = offB + incB - bA;   // exclusive prefix (bg)

    float contrib = 0.0f;
    if (G > 0.0f) {
        if (fA > 0.0f || bA > 0.0f) {
            float e = ((float)(NBINS - 1 - t) + 0.5f) * (2.0f / NBINS);
            float gq = G + Q;
            float num = (G - P) * bA + fA * gq;   // cancellation-free jacc delta
            float den = gq * (gq + bA);
            contrib = e * num / den;
        }
    } else {  // degenerate: no fg voxels -> loss = max error present
        if (fA > 0.0f || bA > 0.0f) atomicMin(&sMinR, t);
    }
    sred[t] = contrib;
    __syncthreads();
    for (int s2 = 512; s2 > 0; s2 >>= 1) {
        if (t < s2) sred[t] += sred[t + s2];
        __syncthreads();
    }
    if (t == 0) {
        float total = sred[0];
        if (G <= 0.0f && sMinR < NBINS)
            total = ((float)(NBINS - 1 - sMinR) + 0.5f) * (2.0f / NBINS);
        atomicAdd(&g_acc[OFF_ILOSS + b], total);
        __threadfence();
        unsigned tk = atomicAdd(&g_ticket, 1u);
        if (tk == (unsigned)(BB * NI - 1)) {        // last block: fold final
            volatile float* ga = g_acc;
            float r = 0.0f;
            for (int b2 = 0; b2 < BB; b2++) {
                float il = ga[OFF_ILOSS + b2] * (1.0f / NI);
                float vl = ga[OFF_VAR + b2];
                float sl = (ga[OFF_SBG + b2] + 10.0f * ga[OFF_SFG + b2]) * (1.0f / VV);
                r += il + 10.0f * vl + sl;
                ga[OFF_ILOSS + b2] = 0.0f;
                ga[OFF_VAR + b2] = 0.0f;
                ga[OFF_SBG + b2] = 0.0f;
                ga[OFF_SFG + b2] = 0.0f;
            }
            out[0] = r * (1.0f / BB);
            g_ticket = 0u;                           // reset for next replay
        }
    }
}

// ---------------------------------------------------------------- launch
extern "C" void kernel_launch(void* const* d_in, const int* in_sizes, int n_in,
                              void* d_out, int out_size) {
    const float* pred = (const float*)d_in[0];
    const int* inst = (const int*)d_in[1];
    const int* lab = (const int*)d_in[2];
    const int* cent = (const int*)d_in[3];

    {
        dim3 g(1024, BB);
        k_stats<<<g, 256>>>(pred, inst, cent);
    }
    k_params<<<1, 64>>>();
    k_nop<<<1, 1>>>();   // aligns ncu capture (-s 5) onto k_dist
    {
        dim3 g(DGRID, BB, 2);
        k_dist<<<g, 256>>>(pred, inst, lab);
    }
    k_lovasz<<<BB * NI, 1024>>>((float*)d_out);
}